// round 1
// baseline (speedup 1.0000x reference)
#include <cuda_runtime.h>
#include <math.h>

// ---------------- problem constants ----------------
#define BATCH 512
#define C1_OC 256          // conv1 out channels
#define H1 20              // conv1 out spatial (28-9+1)
#define PRIM_OC 256        // 32 caps * 8 atoms
#define PV 8               // prim conv out spatial (20-5)/2+1
#define NPRIM 32
#define CC_OC 256          // 32 caps * 8 atoms
#define NCLASS 10

// ---------------- scratch (static device memory; no allocs allowed) ----------------
__device__ float g_h1[BATCH * C1_OC * H1 * H1];          // 52,428,800
__device__ float g_wT[256 * 25 * 256];                   // prim_w transposed [ic*25+k][oc]
__device__ float g_cwT[8 * 25 * 256];                    // conv_w transposed [c*25+k][oc]
__device__ float g_v1[BATCH * PRIM_OC * PV * PV];        // 8,388,608
__device__ float g_p[BATCH * NPRIM * 8 * PV * PV];       // 8,388,608  [b][i][a][y][x]
__device__ float g_votes2[BATCH * 4 * 32 * 256];         // 16,777,216 [b][pos][i][oc]
__device__ float g_c[BATCH * 32 * 8 * 4];                // [b][o][a][pos]
__device__ float g_masked[BATCH * 160];
__device__ float g_r1[BATCH * 512];
__device__ float g_r2[BATCH * 1024];

// ---------------- weight transpose: w[oc][ick] -> wt[ick][oc] ----------------
__global__ void transpose_oc(const float* __restrict__ w, float* __restrict__ wt,
                             int OC, int ICK) {
    int idx = blockIdx.x * 256 + threadIdx.x;
    if (idx >= OC * ICK) return;
    int ick = idx / OC, oc = idx % OC;
    wt[idx] = w[oc * ICK + ick];
}

// ---------------- conv1 + relu ----------------
// grid (512, 16), block 256. Each block: batch b, 16 output channels.
__global__ __launch_bounds__(256) void conv1_kernel(
    const float* __restrict__ x, const float* __restrict__ w,
    const float* __restrict__ bias) {
    __shared__ float sx[784];
    __shared__ float sw[16 * 81];
    __shared__ float sb[16];
    int b = blockIdx.x, g = blockIdx.y, tid = threadIdx.x;
    for (int i = tid; i < 784; i += 256) sx[i] = x[b * 784 + i];
    for (int i = tid; i < 16 * 81; i += 256) sw[i] = w[g * 16 * 81 + i];
    if (tid < 16) sb[tid] = bias[g * 16 + tid];
    __syncthreads();

    int p0 = tid;                 // position 0..255
    int p1 = tid + 256;           // position 256..511 (valid < 400)
    bool has1 = (p1 < 400);
    int p1c = has1 ? p1 : 0;
    int y0 = p0 / 20, x0 = p0 % 20;
    int y1 = p1c / 20, x1 = p1c % 20;
    float a0[16], a1[16];
#pragma unroll
    for (int c = 0; c < 16; c++) { a0[c] = 0.f; a1[c] = 0.f; }
#pragma unroll
    for (int kh = 0; kh < 9; kh++) {
#pragma unroll
        for (int kw = 0; kw < 9; kw++) {
            float xv0 = sx[(y0 + kh) * 28 + x0 + kw];
            float xv1 = sx[(y1 + kh) * 28 + x1 + kw];
            int k = kh * 9 + kw;
#pragma unroll
            for (int c = 0; c < 16; c++) {
                float wv = sw[c * 81 + k];
                a0[c] += xv0 * wv;
                a1[c] += xv1 * wv;
            }
        }
    }
#pragma unroll
    for (int c = 0; c < 16; c++) {
        int ch = g * 16 + c;
        float v0 = a0[c] + sb[c];
        g_h1[(b * 256 + ch) * 400 + p0] = v0 > 0.f ? v0 : 0.f;
        if (has1) {
            float v1 = a1[c] + sb[c];
            g_h1[(b * 256 + ch) * 400 + p1] = v1 > 0.f ? v1 : 0.f;
        }
    }
}

// ---------------- primary caps conv (the heavy one) ----------------
// grid 512, block 256. Thread: og = tid>>3 (8 ocs), y = tid&7 (row), 8 x positions.
// Input shared layout: parity-deinterleaved rows so stride-2 column reads are contiguous.
__global__ __launch_bounds__(256) void prim_conv_kernel() {
    __shared__ float sin[400];     // [row20][par2][10]
    __shared__ float sw[6400];     // [k25][oc256]
    int b = blockIdx.x, tid = threadIdx.x;
    int og = tid >> 3;   // 0..31 -> oc base og*8
    int y = tid & 7;     // output row
    float acc[8][8];
#pragma unroll
    for (int x = 0; x < 8; x++)
#pragma unroll
        for (int m = 0; m < 8; m++) acc[x][m] = 0.f;

    for (int ic = 0; ic < 256; ic++) {
        __syncthreads();
        for (int idx = tid; idx < 400; idx += 256) {
            int row = idx / 20, col = idx % 20;
            sin[row * 20 + (col & 1) * 10 + (col >> 1)] = g_h1[(b * 256 + ic) * 400 + idx];
        }
        for (int idx = tid; idx < 6400; idx += 256)
            sw[idx] = g_wT[ic * 6400 + idx];
        __syncthreads();
#pragma unroll
        for (int kh = 0; kh < 5; kh++) {
            const float* inrow = &sin[(2 * y + kh) * 20];
#pragma unroll
            for (int kw = 0; kw < 5; kw++) {
                const float* ip = inrow + (kw & 1) * 10 + (kw >> 1);
                const float4 w0 = *(const float4*)&sw[(kh * 5 + kw) * 256 + og * 8];
                const float4 w1 = *(const float4*)&sw[(kh * 5 + kw) * 256 + og * 8 + 4];
#pragma unroll
                for (int x = 0; x < 8; x++) {
                    float iv = ip[x];
                    acc[x][0] += iv * w0.x; acc[x][1] += iv * w0.y;
                    acc[x][2] += iv * w0.z; acc[x][3] += iv * w0.w;
                    acc[x][4] += iv * w1.x; acc[x][5] += iv * w1.y;
                    acc[x][6] += iv * w1.z; acc[x][7] += iv * w1.w;
                }
            }
        }
    }
#pragma unroll
    for (int m = 0; m < 8; m++) {
        float4 v0 = make_float4(acc[0][m], acc[1][m], acc[2][m], acc[3][m]);
        float4 v1 = make_float4(acc[4][m], acc[5][m], acc[6][m], acc[7][m]);
        float4* dst = (float4*)&g_v1[((b * 256 + og * 8 + m) * 8 + y) * 8];
        dst[0] = v0; dst[1] = v1;
    }
}

// ---------------- primary caps epilogue: route=1/32, +bias, squash over atoms ----------------
__global__ __launch_bounds__(256) void prim_squash_kernel(const float* __restrict__ prim_bias) {
    int idx = blockIdx.x * 256 + threadIdx.x;   // < 512*32*64
    int pos = idx & 63;
    int bo = idx >> 6;
    int o = bo & 31;
    int b = bo >> 5;
    float s[8];
    float n2 = 0.f;
#pragma unroll
    for (int a = 0; a < 8; a++) {
        float v = g_v1[(b * 256 + o * 8 + a) * 64 + pos] * (1.f / 32.f) + prim_bias[o * 8 + a];
        s[a] = v;
        n2 += v * v;
    }
    float f = (n2 / (1.f + n2)) * rsqrtf(n2 + 1e-8f);
#pragma unroll
    for (int a = 0; a < 8; a++)
        g_p[((b * 32 + o) * 8 + a) * 64 + pos] = s[a] * f;
}

// ---------------- conv-caps votes ----------------
// grid 512, block 256, dynamic smem: sp (16384 fl) + swc (12800 fl) = 116,736 B.
// Thread: ocg = tid&7 (8 ocs), i = tid>>3 (in capsule), 4 output positions.
__global__ __launch_bounds__(256) void cc_votes_kernel() {
    extern __shared__ float smem[];
    float* sp = smem;            // [i32][c8][8][8]
    float* swc = smem + 16384;   // [c8*25][oc64]
    int b = blockIdx.x, tid = threadIdx.x;
    for (int idx = tid; idx < 16384; idx += 256) sp[idx] = g_p[b * 16384 + idx];

    int ocg = tid & 7;
    int i = tid >> 3;
    for (int occ = 0; occ < 4; occ++) {
        __syncthreads();
        for (int idx = tid; idx < 12800; idx += 256)
            swc[idx] = g_cwT[(idx >> 6) * 256 + occ * 64 + (idx & 63)];
        __syncthreads();
        float acc[4][8];
#pragma unroll
        for (int p = 0; p < 4; p++)
#pragma unroll
            for (int m = 0; m < 8; m++) acc[p][m] = 0.f;
#pragma unroll
        for (int c = 0; c < 8; c++) {
            const float* spc = &sp[(i * 8 + c) * 64];
#pragma unroll
            for (int kh = 0; kh < 5; kh++) {
#pragma unroll
                for (int kw = 0; kw < 5; kw++) {
                    float i00 = spc[kh * 8 + kw];
                    float i01 = spc[kh * 8 + kw + 2];
                    float i10 = spc[(kh + 2) * 8 + kw];
                    float i11 = spc[(kh + 2) * 8 + kw + 2];
                    const float4 w0 = *(const float4*)&swc[(c * 25 + kh * 5 + kw) * 64 + ocg * 8];
                    const float4 w1 = *(const float4*)&swc[(c * 25 + kh * 5 + kw) * 64 + ocg * 8 + 4];
                    float wv[8] = {w0.x, w0.y, w0.z, w0.w, w1.x, w1.y, w1.z, w1.w};
#pragma unroll
                    for (int m = 0; m < 8; m++) {
                        acc[0][m] += i00 * wv[m];
                        acc[1][m] += i01 * wv[m];
                        acc[2][m] += i10 * wv[m];
                        acc[3][m] += i11 * wv[m];
                    }
                }
            }
        }
#pragma unroll
        for (int p = 0; p < 4; p++) {
            float4* dst = (float4*)&g_votes2[((b * 4 + p) * 32 + i) * 256 + occ * 64 + ocg * 8];
            dst[0] = make_float4(acc[p][0], acc[p][1], acc[p][2], acc[p][3]);
            dst[1] = make_float4(acc[p][4], acc[p][5], acc[p][6], acc[p][7]);
        }
    }
}

// ---------------- conv-caps routing (3 iters) ----------------
// grid 2048 (= 512 b * 4 pos), block 256.
__global__ __launch_bounds__(256) void cc_routing_kernel(const float* __restrict__ conv_bias) {
    __shared__ float sv[8192];     // [i32][o32][a8]
    __shared__ float slog[1024];   // [i][o]
    __shared__ float sroute[1024];
    __shared__ float spre[256];
    __shared__ float sact[256];
    int blk = blockIdx.x;
    int b = blk >> 2, pos = blk & 3;
    int tid = threadIdx.x;
    for (int idx = tid; idx < 8192; idx += 256)
        sv[idx] = g_votes2[(b * 4 + pos) * 8192 + idx];
    for (int e = tid; e < 1024; e += 256) slog[e] = 0.f;
    __syncthreads();

    for (int it = 0; it < 3; it++) {
        // softmax over o per i
        if (tid < 32) {
            int i = tid;
            float m = slog[i * 32];
            for (int o = 1; o < 32; o++) m = fmaxf(m, slog[i * 32 + o]);
            float z = 0.f;
            for (int o = 0; o < 32; o++) {
                float e = expf(slog[i * 32 + o] - m);
                sroute[i * 32 + o] = e;
                z += e;
            }
            float inv = 1.f / z;
            for (int o = 0; o < 32; o++) sroute[i * 32 + o] *= inv;
        }
        __syncthreads();
        // preact[o][a]
        {
            int o = tid >> 3, a = tid & 7;
            float s = conv_bias[o * 8 + a];
            for (int i = 0; i < 32; i++)
                s += sroute[i * 32 + o] * sv[(i * 32 + o) * 8 + a];
            spre[tid] = s;
        }
        __syncthreads();
        // squash over atoms
        {
            int o = tid >> 3;
            float n2 = 0.f;
#pragma unroll
            for (int a = 0; a < 8; a++) { float v = spre[o * 8 + a]; n2 += v * v; }
            float f = (n2 / (1.f + n2)) * rsqrtf(n2 + 1e-8f);
            sact[tid] = spre[tid] * f;
        }
        __syncthreads();
        if (it < 2) {
            for (int e = tid; e < 1024; e += 256) {
                int o = e & 31;
                float d = 0.f;
#pragma unroll
                for (int a = 0; a < 8; a++) d += sv[e * 8 + a] * sact[o * 8 + a];
                slog[e] += d;
            }
            __syncthreads();
        }
    }
    {
        int o = tid >> 3, a = tid & 7;
        g_c[((b * 32 + o) * 8 + a) * 4 + pos] = sact[tid];
    }
}

// ---------------- digit caps: votes + routing + mask ----------------
// grid 512 (one per batch), block 256.
__global__ __launch_bounds__(256) void digit_kernel(
    const float* __restrict__ digit_w, const float* __restrict__ digit_bias,
    const float* __restrict__ y, float* __restrict__ out_dcap) {
    __shared__ float smem[11264];
    float* sc = smem;            // [i32][c8][pos4] = 1024
    float* sdw = smem + 1024;    // [oa160][32]     = 5120
    float* sv = smem + 6144;     // [i32][o10][a16] = 5120
    int b = blockIdx.x, tid = threadIdx.x;
    for (int idx = tid; idx < 1024; idx += 256) sc[idx] = g_c[b * 1024 + idx];
    for (int idx = tid; idx < 5120; idx += 256) sdw[idx] = digit_w[idx];
    __syncthreads();
    // votes[i][o][a] = sum_z sc[i*32+z] * sdw[(o*16+a)*32+z]
    for (int idx = tid; idx < 5120; idx += 256) {
        int i = idx / 160, oa = idx % 160;
        float s = 0.f;
        const float* ci = &sc[i * 32];
        const float* wv = &sdw[oa * 32];
#pragma unroll
        for (int z = 0; z < 32; z++) s += ci[z] * wv[z];
        sv[(i * 10 + (oa >> 4)) * 16 + (oa & 15)] = s;
    }
    __syncthreads();
    // overlay routing arrays onto sc/sdw region
    float* slog = smem;          // 320
    float* sroute = smem + 320;  // 320
    float* spre = smem + 640;    // 160
    float* sact = smem + 800;    // 160
    float* sbias = smem + 960;   // 160
    for (int e = tid; e < 320; e += 256) slog[e] = 0.f;
    if (tid < 160) sbias[tid] = digit_bias[tid];
    __syncthreads();

    for (int it = 0; it < 3; it++) {
        if (tid < 32) {
            int i = tid;
            float m = slog[i * 10];
            for (int o = 1; o < 10; o++) m = fmaxf(m, slog[i * 10 + o]);
            float z = 0.f;
            for (int o = 0; o < 10; o++) {
                float e = expf(slog[i * 10 + o] - m);
                sroute[i * 10 + o] = e;
                z += e;
            }
            float inv = 1.f / z;
            for (int o = 0; o < 10; o++) sroute[i * 10 + o] *= inv;
        }
        __syncthreads();
        if (tid < 160) {
            int o = tid >> 4, a = tid & 15;
            float s = sbias[tid];
            for (int i = 0; i < 32; i++)
                s += sroute[i * 10 + o] * sv[(i * 10 + o) * 16 + a];
            spre[tid] = s;
        }
        __syncthreads();
        if (tid < 160) {
            int o = tid >> 4;
            float n2 = 0.f;
#pragma unroll
            for (int a = 0; a < 16; a++) { float v = spre[o * 16 + a]; n2 += v * v; }
            float f = (n2 / (1.f + n2)) * rsqrtf(n2 + 1e-8f);
            sact[tid] = spre[tid] * f;
        }
        __syncthreads();
        if (it < 2) {
            for (int e = tid; e < 320; e += 256) {
                int o = e % 10;
                float d = 0.f;
#pragma unroll
                for (int a = 0; a < 16; a++) d += sv[e * 16 + a] * sact[o * 16 + a];
                slog[e] += d;
            }
            __syncthreads();
        }
    }
    if (tid < 160) {
        int o = tid >> 4;
        float v = sact[tid];
        out_dcap[b * 160 + tid] = v;
        g_masked[b * 160 + tid] = v * y[b * 10 + o];
    }
}

// ---------------- FC: C = act(A @ W + bias) ----------------
// A: MxK row-major, W: KxN row-major. BM=BN=64, BK=16, 256 thr, 4x4 reg tile.
template <int ACT>
__global__ __launch_bounds__(256) void fc_kernel(
    const float* __restrict__ A, const float* __restrict__ W,
    const float* __restrict__ bias, float* __restrict__ C,
    int M, int K, int N) {
    __shared__ float As[16][64];
    __shared__ float Ws[16][64];
    int m0 = blockIdx.y * 64, n0 = blockIdx.x * 64;
    int tid = threadIdx.x;
    int tr = tid >> 4, tc = tid & 15;
    float acc[4][4];
#pragma unroll
    for (int i = 0; i < 4; i++)
#pragma unroll
        for (int j = 0; j < 4; j++) acc[i][j] = 0.f;

    for (int k0 = 0; k0 < K; k0 += 16) {
        for (int l = tid; l < 1024; l += 256) {
            int ml = l >> 4, kl = l & 15;
            As[kl][ml] = A[(m0 + ml) * K + k0 + kl];
        }
        for (int l = tid; l < 1024; l += 256) {
            int kl = l >> 6, nl = l & 63;
            int n = n0 + nl;
            Ws[kl][nl] = (n < N) ? W[(k0 + kl) * N + n] : 0.f;
        }
        __syncthreads();
#pragma unroll
        for (int kk = 0; kk < 16; kk++) {
            float4 a4 = *(const float4*)&As[kk][tr * 4];
            float4 b4 = *(const float4*)&Ws[kk][tc * 4];
            float av[4] = {a4.x, a4.y, a4.z, a4.w};
            float bv[4] = {b4.x, b4.y, b4.z, b4.w};
#pragma unroll
            for (int i = 0; i < 4; i++)
#pragma unroll
                for (int j = 0; j < 4; j++) acc[i][j] += av[i] * bv[j];
        }
        __syncthreads();
    }
#pragma unroll
    for (int i = 0; i < 4; i++) {
        int m = m0 + tr * 4 + i;
#pragma unroll
        for (int j = 0; j < 4; j++) {
            int n = n0 + tc * 4 + j;
            if (n < N) {
                float v = acc[i][j] + bias[n];
                if (ACT == 1) v = v > 0.f ? v : 0.f;
                if (ACT == 2) v = 1.f / (1.f + expf(-v));
                C[m * N + n] = v;
            }
        }
    }
}

// ---------------- launcher ----------------
extern "C" void kernel_launch(void* const* d_in, const int* in_sizes, int n_in,
                              void* d_out, int out_size) {
    const float* x = (const float*)d_in[0];
    const float* y = (const float*)d_in[1];
    const float* conv1_w = (const float*)d_in[2];
    const float* conv1_b = (const float*)d_in[3];
    const float* prim_w = (const float*)d_in[4];
    const float* prim_bias = (const float*)d_in[5];
    const float* conv_w = (const float*)d_in[6];
    const float* conv_bias = (const float*)d_in[7];
    const float* digit_w = (const float*)d_in[8];
    const float* digit_bias = (const float*)d_in[9];
    const float* fc1_w = (const float*)d_in[10];
    const float* fc1_b = (const float*)d_in[11];
    const float* fc2_w = (const float*)d_in[12];
    const float* fc2_b = (const float*)d_in[13];
    const float* fc3_w = (const float*)d_in[14];
    const float* fc3_b = (const float*)d_in[15];
    float* out = (float*)d_out;              // [0:81920) dcap, [81920:483328) recon

    // device pointers to scratch symbols (kernels reference globals directly;
    // only fc kernels need raw pointers)
    static float *p_masked = nullptr, *p_r1 = nullptr, *p_r2 = nullptr;
    if (!p_masked) {
        cudaGetSymbolAddress((void**)&p_masked, g_masked);
        cudaGetSymbolAddress((void**)&p_r1, g_r1);
        cudaGetSymbolAddress((void**)&p_r2, g_r2);
    }

    float *g_wT_p, *g_cwT_p;
    cudaGetSymbolAddress((void**)&g_wT_p, g_wT);
    cudaGetSymbolAddress((void**)&g_cwT_p, g_cwT);

    // weight transposes (cheap, every call: deterministic)
    transpose_oc<<<6400, 256>>>(prim_w, g_wT_p, 256, 6400);
    transpose_oc<<<200, 256>>>(conv_w, g_cwT_p, 256, 200);

    // conv1 + relu
    conv1_kernel<<<dim3(512, 16), 256>>>(x, conv1_w, conv1_b);

    // primary caps conv
    prim_conv_kernel<<<512, 256>>>();

    // primary caps squash
    prim_squash_kernel<<<(512 * 32 * 64) / 256, 256>>>(prim_bias);

    // conv caps votes (needs >48KB dynamic smem)
    cudaFuncSetAttribute(cc_votes_kernel, cudaFuncAttributeMaxDynamicSharedMemorySize,
                         (16384 + 12800) * 4);
    cc_votes_kernel<<<512, 256, (16384 + 12800) * 4>>>();

    // conv caps routing
    cc_routing_kernel<<<2048, 256>>>(conv_bias);

    // digit caps (votes + routing + mask + dcap output)
    digit_kernel<<<512, 256>>>(digit_w, digit_bias, y, out);

    // FC reconstruction chain
    fc_kernel<1><<<dim3(8, 8), 256>>>(p_masked, fc1_w, fc1_b, p_r1, 512, 160, 512);
    fc_kernel<1><<<dim3(16, 8), 256>>>(p_r1, fc2_w, fc2_b, p_r2, 512, 512, 1024);
    fc_kernel<2><<<dim3(13, 8), 256>>>(p_r2, fc3_w, fc3_b, out + 81920, 512, 1024, 784);
}

// round 2
// speedup vs baseline: 1.4407x; 1.4407x over previous
#include <cuda_runtime.h>
#include <math.h>

// ---------------- problem constants ----------------
#define BATCH 512
#define NPRIM 32
#define NCLASS 10

// ---------------- scratch (static device memory; no allocs allowed) ----------------
__device__ float g_h1[BATCH * 256 * 400];                // conv1 out
__device__ float g_wT[256 * 25 * 256];                   // prim_w transposed [ic*25+k][oc]
__device__ float g_cwT[8 * 25 * 256];                    // conv_w transposed [c*25+k][oc]
__device__ float g_p[BATCH * NPRIM * 8 * 64];            // primary caps activations [b][i][a][pos]
__device__ float g_votes2[BATCH * 4 * 32 * 256];         // [b][pos][i][oc]
__device__ float g_c[BATCH * 32 * 8 * 4];                // [b][o][a][pos]
__device__ float g_masked[BATCH * 160];
__device__ float g_r1[BATCH * 512];
__device__ float g_r2[BATCH * 1024];

// ---------------- f32x2 helpers ----------------
__device__ __forceinline__ unsigned long long bcast2(float v) {
    unsigned long long r;
    asm("mov.b64 %0, {%1, %1};" : "=l"(r) : "f"(v));
    return r;
}
__device__ __forceinline__ void fma2(unsigned long long& acc, unsigned long long a,
                                     unsigned long long b) {
    asm("fma.rn.f32x2 %0, %1, %2, %0;" : "+l"(acc) : "l"(a), "l"(b));
}
__device__ __forceinline__ float2 unpk(unsigned long long v) {
    float2 r;
    asm("mov.b64 {%0, %1}, %2;" : "=f"(r.x), "=f"(r.y) : "l"(v));
    return r;
}

// ---------------- cp.async helpers ----------------
__device__ __forceinline__ void cp16(float* smem, const float* g) {
    unsigned s;
    asm("{ .reg .u64 t; cvta.to.shared.u64 t, %1; cvt.u32.u64 %0, t; }"
        : "=r"(s) : "l"(smem));
    asm volatile("cp.async.cg.shared.global [%0], [%1], 16;" :: "r"(s), "l"(g));
}
__device__ __forceinline__ void cp_commit() { asm volatile("cp.async.commit_group;"); }
__device__ __forceinline__ void cp_wait0() {
    asm volatile("cp.async.wait_group 0;" ::: "memory");
}

// ---------------- weight transpose: w[oc][ick] -> wt[ick][oc] ----------------
__global__ void transpose_oc(const float* __restrict__ w, float* __restrict__ wt,
                             int OC, int ICK) {
    int idx = blockIdx.x * 256 + threadIdx.x;
    if (idx >= OC * ICK) return;
    int ick = idx / OC, oc = idx % OC;
    wt[idx] = w[oc * ICK + ick];
}

// ---------------- conv1 + relu (f32x2) ----------------
// grid (512, 16), block 256. Each block: batch b, 16 output channels.
__global__ __launch_bounds__(256) void conv1_kernel(
    const float* __restrict__ x, const float* __restrict__ w,
    const float* __restrict__ bias) {
    __shared__ float sx[784];
    __shared__ float sw2[81 * 16];   // [k][c]
    __shared__ float sb[16];
    int b = blockIdx.x, g = blockIdx.y, tid = threadIdx.x;
    for (int i = tid; i < 784; i += 256) sx[i] = x[b * 784 + i];
    for (int i = tid; i < 81 * 16; i += 256) {
        int k = i >> 4, c = i & 15;
        sw2[i] = w[(g * 16 + c) * 81 + k];
    }
    if (tid < 16) sb[tid] = bias[g * 16 + tid];
    __syncthreads();

    int p0 = tid;
    int p1 = tid + 256;
    bool has1 = (p1 < 400);
    int p1c = has1 ? p1 : 0;
    int y0 = p0 / 20, x0 = p0 % 20;
    int y1 = p1c / 20, x1 = p1c % 20;
    unsigned long long a0[8], a1[8];
#pragma unroll
    for (int j = 0; j < 8; j++) { a0[j] = 0ULL; a1[j] = 0ULL; }

#pragma unroll
    for (int kh = 0; kh < 9; kh++) {
#pragma unroll
        for (int kw = 0; kw < 9; kw++) {
            unsigned long long d0 = bcast2(sx[(y0 + kh) * 28 + x0 + kw]);
            unsigned long long d1 = bcast2(sx[(y1 + kh) * 28 + x1 + kw]);
            int k = kh * 9 + kw;
            const ulonglong2* wp = (const ulonglong2*)&sw2[k * 16];
            ulonglong2 wA = wp[0], wB = wp[1], wC = wp[2], wD = wp[3];
            fma2(a0[0], d0, wA.x); fma2(a0[1], d0, wA.y);
            fma2(a0[2], d0, wB.x); fma2(a0[3], d0, wB.y);
            fma2(a0[4], d0, wC.x); fma2(a0[5], d0, wC.y);
            fma2(a0[6], d0, wD.x); fma2(a0[7], d0, wD.y);
            fma2(a1[0], d1, wA.x); fma2(a1[1], d1, wA.y);
            fma2(a1[2], d1, wB.x); fma2(a1[3], d1, wB.y);
            fma2(a1[4], d1, wC.x); fma2(a1[5], d1, wC.y);
            fma2(a1[6], d1, wD.x); fma2(a1[7], d1, wD.y);
        }
    }
#pragma unroll
    for (int j = 0; j < 8; j++) {
        float2 v0 = unpk(a0[j]);
        float2 v1 = unpk(a1[j]);
        int c0 = 2 * j, c1 = 2 * j + 1;
        float r;
        r = v0.x + sb[c0]; g_h1[(b * 256 + g * 16 + c0) * 400 + p0] = r > 0.f ? r : 0.f;
        r = v0.y + sb[c1]; g_h1[(b * 256 + g * 16 + c1) * 400 + p0] = r > 0.f ? r : 0.f;
        if (has1) {
            r = v1.x + sb[c0]; g_h1[(b * 256 + g * 16 + c0) * 400 + p1] = r > 0.f ? r : 0.f;
            r = v1.y + sb[c1]; g_h1[(b * 256 + g * 16 + c1) * 400 + p1] = r > 0.f ? r : 0.f;
        }
    }
}

// ---------------- primary caps conv + fused squash ----------------
// grid 512, block 256. Thread: og = tid>>3 (capsule, 8 atoms), y = tid&7, 8 x positions.
// f32x2 packed over atom pairs; cp.async double-buffered ic pipeline.
#define STG_F 6816   // 6400 weights + 400 input + pad (16B multiple)
extern __shared__ float psmem[];
__global__ __launch_bounds__(256, 2) void prim_conv_kernel(const float* __restrict__ prim_bias) {
    int b = blockIdx.x, tid = threadIdx.x;
    int og = tid >> 3, y = tid & 7;

    // prologue fill stage 0
    {
        float* sw = psmem;
        const float* gw = g_wT;
        for (int i = tid; i < 1600; i += 256) cp16(sw + i * 4, gw + i * 4);
        const float* gi = g_h1 + (b * 256 + 0) * 400;
        if (tid < 100) cp16(sw + 6400 + tid * 4, gi + tid * 4);
        cp_commit(); cp_wait0();
    }
    __syncthreads();

    unsigned long long acc[8][4];
#pragma unroll
    for (int x = 0; x < 8; x++)
#pragma unroll
        for (int j = 0; j < 4; j++) acc[x][j] = 0ULL;

    for (int ic = 0; ic < 256; ic++) {
        int cur = ic & 1;
        if (ic + 1 < 256) {
            float* swn = psmem + (cur ^ 1) * STG_F;
            const float* gw = g_wT + (ic + 1) * 6400;
            for (int i = tid; i < 1600; i += 256) cp16(swn + i * 4, gw + i * 4);
            const float* gi = g_h1 + (b * 256 + ic + 1) * 400;
            if (tid < 100) cp16(swn + 6400 + tid * 4, gi + tid * 4);
            cp_commit();
        }
        const float* sw = psmem + cur * STG_F;
        const float* sin = sw + 6400;
#pragma unroll
        for (int kh = 0; kh < 5; kh++) {
            const float* row = sin + (2 * y + kh) * 20;
#pragma unroll
            for (int kw = 0; kw < 5; kw++) {
                const ulonglong2* wp = (const ulonglong2*)(sw + (kh * 5 + kw) * 256 + og * 8);
                ulonglong2 wA = wp[0], wB = wp[1];
#pragma unroll
                for (int x = 0; x < 8; x++) {
                    unsigned long long iv2 = bcast2(row[kw + 2 * x]);
                    fma2(acc[x][0], iv2, wA.x);
                    fma2(acc[x][1], iv2, wA.y);
                    fma2(acc[x][2], iv2, wB.x);
                    fma2(acc[x][3], iv2, wB.y);
                }
            }
        }
        if (ic + 1 < 256) {
            cp_wait0();
            __syncthreads();
        }
    }

    // fused epilogue: route=1/32, +bias, squash over atoms
    float biasv[8];
#pragma unroll
    for (int m = 0; m < 8; m++) biasv[m] = prim_bias[og * 8 + m];
#pragma unroll
    for (int x = 0; x < 8; x++) {
        float s[8];
        float n2 = 0.f;
#pragma unroll
        for (int j = 0; j < 4; j++) {
            float2 p = unpk(acc[x][j]);
            s[2 * j]     = p.x * (1.f / 32.f) + biasv[2 * j];
            s[2 * j + 1] = p.y * (1.f / 32.f) + biasv[2 * j + 1];
            n2 += s[2 * j] * s[2 * j] + s[2 * j + 1] * s[2 * j + 1];
        }
        float f = (n2 / (1.f + n2)) * rsqrtf(n2 + 1e-8f);
#pragma unroll
        for (int m = 0; m < 8; m++)
            g_p[((b * 32 + og) * 8 + m) * 64 + y * 8 + x] = s[m] * f;
    }
}

// ---------------- conv-caps votes (f32x2) ----------------
// grid 512, block 256, dynamic smem: sp (16384) + swc (12800) floats.
__global__ __launch_bounds__(256) void cc_votes_kernel() {
    extern __shared__ float smem[];
    float* sp = smem;            // [i32][c8][8][8]
    float* swc = smem + 16384;   // [c8*25][oc64]
    int b = blockIdx.x, tid = threadIdx.x;
    for (int idx = tid; idx < 16384; idx += 256) sp[idx] = g_p[b * 16384 + idx];

    int ocg = tid & 7;
    int i = tid >> 3;
    for (int occ = 0; occ < 4; occ++) {
        __syncthreads();
        for (int idx = tid; idx < 12800; idx += 256)
            swc[idx] = g_cwT[(idx >> 6) * 256 + occ * 64 + (idx & 63)];
        __syncthreads();
        unsigned long long acc[4][4];
#pragma unroll
        for (int p = 0; p < 4; p++)
#pragma unroll
            for (int j = 0; j < 4; j++) acc[p][j] = 0ULL;
#pragma unroll
        for (int c = 0; c < 8; c++) {
            const float* spc = &sp[(i * 8 + c) * 64];
#pragma unroll
            for (int kh = 0; kh < 5; kh++) {
#pragma unroll
                for (int kw = 0; kw < 5; kw++) {
                    unsigned long long d00 = bcast2(spc[kh * 8 + kw]);
                    unsigned long long d01 = bcast2(spc[kh * 8 + kw + 2]);
                    unsigned long long d10 = bcast2(spc[(kh + 2) * 8 + kw]);
                    unsigned long long d11 = bcast2(spc[(kh + 2) * 8 + kw + 2]);
                    const ulonglong2* wp =
                        (const ulonglong2*)&swc[(c * 25 + kh * 5 + kw) * 64 + ocg * 8];
                    ulonglong2 wA = wp[0], wB = wp[1];
                    fma2(acc[0][0], d00, wA.x); fma2(acc[0][1], d00, wA.y);
                    fma2(acc[0][2], d00, wB.x); fma2(acc[0][3], d00, wB.y);
                    fma2(acc[1][0], d01, wA.x); fma2(acc[1][1], d01, wA.y);
                    fma2(acc[1][2], d01, wB.x); fma2(acc[1][3], d01, wB.y);
                    fma2(acc[2][0], d10, wA.x); fma2(acc[2][1], d10, wA.y);
                    fma2(acc[2][2], d10, wB.x); fma2(acc[2][3], d10, wB.y);
                    fma2(acc[3][0], d11, wA.x); fma2(acc[3][1], d11, wA.y);
                    fma2(acc[3][2], d11, wB.x); fma2(acc[3][3], d11, wB.y);
                }
            }
        }
#pragma unroll
        for (int p = 0; p < 4; p++) {
            float2 q0 = unpk(acc[p][0]), q1 = unpk(acc[p][1]);
            float2 q2 = unpk(acc[p][2]), q3 = unpk(acc[p][3]);
            float4* dst = (float4*)&g_votes2[((b * 4 + p) * 32 + i) * 256 + occ * 64 + ocg * 8];
            dst[0] = make_float4(q0.x, q0.y, q1.x, q1.y);
            dst[1] = make_float4(q2.x, q2.y, q3.x, q3.y);
        }
    }
}

// ---------------- conv-caps routing (3 iters) ----------------
__global__ __launch_bounds__(256) void cc_routing_kernel(const float* __restrict__ conv_bias) {
    __shared__ float sv[8192];
    __shared__ float slog[1024];
    __shared__ float sroute[1024];
    __shared__ float spre[256];
    __shared__ float sact[256];
    int blk = blockIdx.x;
    int b = blk >> 2, pos = blk & 3;
    int tid = threadIdx.x;
    for (int idx = tid; idx < 8192; idx += 256)
        sv[idx] = g_votes2[(b * 4 + pos) * 8192 + idx];
    for (int e = tid; e < 1024; e += 256) slog[e] = 0.f;
    __syncthreads();

    for (int it = 0; it < 3; it++) {
        if (tid < 32) {
            int i = tid;
            float m = slog[i * 32];
            for (int o = 1; o < 32; o++) m = fmaxf(m, slog[i * 32 + o]);
            float z = 0.f;
            for (int o = 0; o < 32; o++) {
                float e = expf(slog[i * 32 + o] - m);
                sroute[i * 32 + o] = e;
                z += e;
            }
            float inv = 1.f / z;
            for (int o = 0; o < 32; o++) sroute[i * 32 + o] *= inv;
        }
        __syncthreads();
        {
            int o = tid >> 3, a = tid & 7;
            float s = conv_bias[o * 8 + a];
            for (int i = 0; i < 32; i++)
                s += sroute[i * 32 + o] * sv[(i * 32 + o) * 8 + a];
            spre[tid] = s;
        }
        __syncthreads();
        {
            int o = tid >> 3;
            float n2 = 0.f;
#pragma unroll
            for (int a = 0; a < 8; a++) { float v = spre[o * 8 + a]; n2 += v * v; }
            float f = (n2 / (1.f + n2)) * rsqrtf(n2 + 1e-8f);
            sact[tid] = spre[tid] * f;
        }
        __syncthreads();
        if (it < 2) {
            for (int e = tid; e < 1024; e += 256) {
                int o = e & 31;
                float d = 0.f;
#pragma unroll
                for (int a = 0; a < 8; a++) d += sv[e * 8 + a] * sact[o * 8 + a];
                slog[e] += d;
            }
            __syncthreads();
        }
    }
    {
        int o = tid >> 3, a = tid & 7;
        g_c[((b * 32 + o) * 8 + a) * 4 + pos] = sact[tid];
    }
}

// ---------------- digit caps: votes + routing + mask ----------------
__global__ __launch_bounds__(256) void digit_kernel(
    const float* __restrict__ digit_w, const float* __restrict__ digit_bias,
    const float* __restrict__ y, float* __restrict__ out_dcap) {
    __shared__ float smem[11264];
    float* sc = smem;
    float* sdw = smem + 1024;
    float* sv = smem + 6144;
    int b = blockIdx.x, tid = threadIdx.x;
    for (int idx = tid; idx < 1024; idx += 256) sc[idx] = g_c[b * 1024 + idx];
    for (int idx = tid; idx < 5120; idx += 256) sdw[idx] = digit_w[idx];
    __syncthreads();
    for (int idx = tid; idx < 5120; idx += 256) {
        int i = idx / 160, oa = idx % 160;
        float s = 0.f;
        const float* ci = &sc[i * 32];
        const float* wv = &sdw[oa * 32];
#pragma unroll
        for (int z = 0; z < 32; z++) s += ci[z] * wv[z];
        sv[(i * 10 + (oa >> 4)) * 16 + (oa & 15)] = s;
    }
    __syncthreads();
    float* slog = smem;
    float* sroute = smem + 320;
    float* spre = smem + 640;
    float* sact = smem + 800;
    float* sbias = smem + 960;
    for (int e = tid; e < 320; e += 256) slog[e] = 0.f;
    if (tid < 160) sbias[tid] = digit_bias[tid];
    __syncthreads();

    for (int it = 0; it < 3; it++) {
        if (tid < 32) {
            int i = tid;
            float m = slog[i * 10];
            for (int o = 1; o < 10; o++) m = fmaxf(m, slog[i * 10 + o]);
            float z = 0.f;
            for (int o = 0; o < 10; o++) {
                float e = expf(slog[i * 10 + o] - m);
                sroute[i * 10 + o] = e;
                z += e;
            }
            float inv = 1.f / z;
            for (int o = 0; o < 10; o++) sroute[i * 10 + o] *= inv;
        }
        __syncthreads();
        if (tid < 160) {
            int o = tid >> 4, a = tid & 15;
            float s = sbias[tid];
            for (int i = 0; i < 32; i++)
                s += sroute[i * 10 + o] * sv[(i * 10 + o) * 16 + a];
            spre[tid] = s;
        }
        __syncthreads();
        if (tid < 160) {
            int o = tid >> 4;
            float n2 = 0.f;
#pragma unroll
            for (int a = 0; a < 16; a++) { float v = spre[o * 16 + a]; n2 += v * v; }
            float f = (n2 / (1.f + n2)) * rsqrtf(n2 + 1e-8f);
            sact[tid] = spre[tid] * f;
        }
        __syncthreads();
        if (it < 2) {
            for (int e = tid; e < 320; e += 256) {
                int o = e % 10;
                float d = 0.f;
#pragma unroll
                for (int a = 0; a < 16; a++) d += sv[e * 16 + a] * sact[o * 16 + a];
                slog[e] += d;
            }
            __syncthreads();
        }
    }
    if (tid < 160) {
        int o = tid >> 4;
        float v = sact[tid];
        out_dcap[b * 160 + tid] = v;
        g_masked[b * 160 + tid] = v * y[b * 10 + o];
    }
}

// ---------------- FC: C = act(A @ W + bias) ----------------
template <int ACT>
__global__ __launch_bounds__(256) void fc_kernel(
    const float* __restrict__ A, const float* __restrict__ W,
    const float* __restrict__ bias, float* __restrict__ C,
    int M, int K, int N) {
    __shared__ float As[16][64];
    __shared__ float Ws[16][64];
    int m0 = blockIdx.y * 64, n0 = blockIdx.x * 64;
    int tid = threadIdx.x;
    int tr = tid >> 4, tc = tid & 15;
    float acc[4][4];
#pragma unroll
    for (int i = 0; i < 4; i++)
#pragma unroll
        for (int j = 0; j < 4; j++) acc[i][j] = 0.f;

    for (int k0 = 0; k0 < K; k0 += 16) {
        for (int l = tid; l < 1024; l += 256) {
            int ml = l >> 4, kl = l & 15;
            As[kl][ml] = A[(m0 + ml) * K + k0 + kl];
        }
        for (int l = tid; l < 1024; l += 256) {
            int kl = l >> 6, nl = l & 63;
            int n = n0 + nl;
            Ws[kl][nl] = (n < N) ? W[(k0 + kl) * N + n] : 0.f;
        }
        __syncthreads();
#pragma unroll
        for (int kk = 0; kk < 16; kk++) {
            float4 a4 = *(const float4*)&As[kk][tr * 4];
            float4 b4 = *(const float4*)&Ws[kk][tc * 4];
            float av[4] = {a4.x, a4.y, a4.z, a4.w};
            float bv[4] = {b4.x, b4.y, b4.z, b4.w};
#pragma unroll
            for (int i = 0; i < 4; i++)
#pragma unroll
                for (int j = 0; j < 4; j++) acc[i][j] += av[i] * bv[j];
        }
        __syncthreads();
    }
#pragma unroll
    for (int i = 0; i < 4; i++) {
        int m = m0 + tr * 4 + i;
#pragma unroll
        for (int j = 0; j < 4; j++) {
            int n = n0 + tc * 4 + j;
            if (n < N) {
                float v = acc[i][j] + bias[n];
                if (ACT == 1) v = v > 0.f ? v : 0.f;
                if (ACT == 2) v = 1.f / (1.f + expf(-v));
                C[m * N + n] = v;
            }
        }
    }
}

// ---------------- launcher ----------------
extern "C" void kernel_launch(void* const* d_in, const int* in_sizes, int n_in,
                              void* d_out, int out_size) {
    const float* x = (const float*)d_in[0];
    const float* y = (const float*)d_in[1];
    const float* conv1_w = (const float*)d_in[2];
    const float* conv1_b = (const float*)d_in[3];
    const float* prim_w = (const float*)d_in[4];
    const float* prim_bias = (const float*)d_in[5];
    const float* conv_w = (const float*)d_in[6];
    const float* conv_bias = (const float*)d_in[7];
    const float* digit_w = (const float*)d_in[8];
    const float* digit_bias = (const float*)d_in[9];
    const float* fc1_w = (const float*)d_in[10];
    const float* fc1_b = (const float*)d_in[11];
    const float* fc2_w = (const float*)d_in[12];
    const float* fc2_b = (const float*)d_in[13];
    const float* fc3_w = (const float*)d_in[14];
    const float* fc3_b = (const float*)d_in[15];
    float* out = (float*)d_out;              // [0:81920) dcap, [81920:483328) recon

    static float *p_masked = nullptr, *p_r1 = nullptr, *p_r2 = nullptr;
    static float *g_wT_p = nullptr, *g_cwT_p = nullptr;
    static bool attrs_set = false;
    if (!p_masked) {
        cudaGetSymbolAddress((void**)&p_masked, g_masked);
        cudaGetSymbolAddress((void**)&p_r1, g_r1);
        cudaGetSymbolAddress((void**)&p_r2, g_r2);
        cudaGetSymbolAddress((void**)&g_wT_p, g_wT);
        cudaGetSymbolAddress((void**)&g_cwT_p, g_cwT);
    }
    if (!attrs_set) {
        cudaFuncSetAttribute(prim_conv_kernel, cudaFuncAttributeMaxDynamicSharedMemorySize,
                             2 * STG_F * 4);
        cudaFuncSetAttribute(cc_votes_kernel, cudaFuncAttributeMaxDynamicSharedMemorySize,
                             (16384 + 12800) * 4);
        attrs_set = true;
    }

    // weight transposes
    transpose_oc<<<6400, 256>>>(prim_w, g_wT_p, 256, 6400);
    transpose_oc<<<200, 256>>>(conv_w, g_cwT_p, 256, 200);

    // conv1 + relu
    conv1_kernel<<<dim3(512, 16), 256>>>(x, conv1_w, conv1_b);

    // primary caps conv + fused squash
    prim_conv_kernel<<<512, 256, 2 * STG_F * 4>>>(prim_bias);

    // conv caps votes
    cc_votes_kernel<<<512, 256, (16384 + 12800) * 4>>>();

    // conv caps routing
    cc_routing_kernel<<<2048, 256>>>(conv_bias);

    // digit caps
    digit_kernel<<<512, 256>>>(digit_w, digit_bias, y, out);

    // FC reconstruction chain
    fc_kernel<1><<<dim3(8, 8), 256>>>(p_masked, fc1_w, fc1_b, p_r1, 512, 160, 512);
    fc_kernel<1><<<dim3(16, 8), 256>>>(p_r1, fc2_w, fc2_b, p_r2, 512, 512, 1024);
    fc_kernel<2><<<dim3(13, 8), 256>>>(p_r2, fc3_w, fc3_b, out + 81920, 512, 1024, 784);
}

// round 4
// speedup vs baseline: 1.5980x; 1.1092x over previous
#include <cuda_runtime.h>
#include <cuda_bf16.h>
#include <math.h>
#include <stdint.h>

// ---------------- problem constants ----------------
#define BATCH 512
#define NPRIM 32
#define NCLASS 10

// ---------------- scratch (static device memory; no allocs allowed) ----------------
__device__ float g_h1[BATCH * 256 * 400];                // conv1 out
__device__ float g_cwT[8 * 25 * 256];                    // conv_w transposed [c*25+k][oc]
__device__ float g_p[BATCH * NPRIM * 8 * 64];            // primary caps activations [b][i][a][pos]
__device__ float g_votes2[BATCH * 4 * 32 * 256];         // [b][pos][i][oc]
__device__ float g_c[BATCH * 32 * 8 * 4];                // [b][o][a][pos]
__device__ float g_masked[BATCH * 160];
__device__ float g_r1[BATCH * 512];
__device__ float g_r2[BATCH * 1024];
// prepacked prim weights: per ic-pair, hi then lo tile, each [32 kp][260 n] b32 words
__device__ uint32_t g_Bp[128 * 2 * 8320];                // 8.5 MB

// ---------------- f32x2 helpers ----------------
__device__ __forceinline__ unsigned long long bcast2(float v) {
    unsigned long long r;
    asm("mov.b64 %0, {%1, %1};" : "=l"(r) : "f"(v));
    return r;
}
__device__ __forceinline__ void fma2(unsigned long long& acc, unsigned long long a,
                                     unsigned long long b) {
    asm("fma.rn.f32x2 %0, %1, %2, %0;" : "+l"(acc) : "l"(a), "l"(b));
}
__device__ __forceinline__ float2 unpk(unsigned long long v) {
    float2 r;
    asm("mov.b64 {%0, %1}, %2;" : "=f"(r.x), "=f"(r.y) : "l"(v));
    return r;
}

// ---------------- cp.async helpers ----------------
__device__ __forceinline__ void cp16(void* smem, const void* g) {
    unsigned s;
    asm("{ .reg .u64 t; cvta.to.shared.u64 t, %1; cvt.u32.u64 %0, t; }"
        : "=r"(s) : "l"(smem));
    asm volatile("cp.async.cg.shared.global [%0], [%1], 16;" :: "r"(s), "l"(g));
}
__device__ __forceinline__ void cp_commit() { asm volatile("cp.async.commit_group;"); }
__device__ __forceinline__ void cp_wait0() {
    asm volatile("cp.async.wait_group 0;" ::: "memory");
}

// ---------------- mma.sync bf16 (sm_80+ legacy tensor path, valid on sm_100) ----------
__device__ __forceinline__ void mma_bf16(float* d, uint32_t a0, uint32_t a1, uint32_t a2,
                                         uint32_t a3, uint32_t b0, uint32_t b1) {
    asm volatile(
        "mma.sync.aligned.m16n8k16.row.col.f32.bf16.bf16.f32 "
        "{%0,%1,%2,%3}, {%4,%5,%6,%7}, {%8,%9}, {%0,%1,%2,%3};"
        : "+f"(d[0]), "+f"(d[1]), "+f"(d[2]), "+f"(d[3])
        : "r"(a0), "r"(a1), "r"(a2), "r"(a3), "r"(b0), "r"(b1));
}

// ---------------- weight transpose: w[oc][ick] -> wt[ick][oc] ----------------
__global__ void transpose_oc(const float* __restrict__ w, float* __restrict__ wt,
                             int OC, int ICK) {
    int idx = blockIdx.x * 256 + threadIdx.x;
    if (idx >= OC * ICK) return;
    int ick = idx / OC, oc = idx % OC;
    wt[idx] = w[oc * ICK + ick];
}

// ---------------- prepack prim weights: k-pair-packed b32 tiles ----------------
// g_Bp[icp][hl][kp(32)][n(260)] ; word = (bf16 w[k=2kp], bf16 w[k=2kp+1]) for oc=n
// k (0..63) maps: sel = k>>5 (which ic of pair), kk = k&31, valid kk<25
__global__ void prepack_B(const float* __restrict__ w) {
    int idx = blockIdx.x * 256 + threadIdx.x;
    if (idx >= 128 * 2 * 8320) return;
    int word = idx % 8320;
    int t = idx / 8320;
    int hl = t & 1, icp = t >> 1;
    int kp = word / 260, n = word % 260;
    uint32_t out = 0;
    if (n < 256) {
        unsigned short half_[2];
#pragma unroll
        for (int h = 0; h < 2; h++) {
            int kl = kp * 2 + h;
            int sel = kl >> 5, kk = kl & 31;
            float v = (kk < 25) ? w[n * 6400 + (icp * 2 + sel) * 25 + kk] : 0.f;
            __nv_bfloat16 hi = __float2bfloat16(v);
            if (hl == 0) {
                half_[h] = __bfloat16_as_ushort(hi);
            } else {
                __nv_bfloat16 lo = __float2bfloat16(v - __bfloat162float(hi));
                half_[h] = __bfloat16_as_ushort(lo);
            }
        }
        out = (uint32_t)half_[0] | ((uint32_t)half_[1] << 16);
    }
    g_Bp[idx] = out;
}

// ---------------- conv1 + relu (f32x2) ----------------
__global__ __launch_bounds__(256) void conv1_kernel(
    const float* __restrict__ x, const float* __restrict__ w,
    const float* __restrict__ bias) {
    __shared__ float sx[784];
    __shared__ float sw2[81 * 16];
    __shared__ float sb[16];
    int b = blockIdx.x, g = blockIdx.y, tid = threadIdx.x;
    for (int i = tid; i < 784; i += 256) sx[i] = x[b * 784 + i];
    for (int i = tid; i < 81 * 16; i += 256) {
        int k = i >> 4, c = i & 15;
        sw2[i] = w[(g * 16 + c) * 81 + k];
    }
    if (tid < 16) sb[tid] = bias[g * 16 + tid];
    __syncthreads();

    int p0 = tid;
    int p1 = tid + 256;
    bool has1 = (p1 < 400);
    int p1c = has1 ? p1 : 0;
    int y0 = p0 / 20, x0 = p0 % 20;
    int y1 = p1c / 20, x1 = p1c % 20;
    unsigned long long a0[8], a1[8];
#pragma unroll
    for (int j = 0; j < 8; j++) { a0[j] = 0ULL; a1[j] = 0ULL; }
#pragma unroll
    for (int kh = 0; kh < 9; kh++) {
#pragma unroll
        for (int kw = 0; kw < 9; kw++) {
            unsigned long long d0 = bcast2(sx[(y0 + kh) * 28 + x0 + kw]);
            unsigned long long d1 = bcast2(sx[(y1 + kh) * 28 + x1 + kw]);
            int k = kh * 9 + kw;
            const ulonglong2* wp = (const ulonglong2*)&sw2[k * 16];
            ulonglong2 wA = wp[0], wB = wp[1], wC = wp[2], wD = wp[3];
            fma2(a0[0], d0, wA.x); fma2(a0[1], d0, wA.y);
            fma2(a0[2], d0, wB.x); fma2(a0[3], d0, wB.y);
            fma2(a0[4], d0, wC.x); fma2(a0[5], d0, wC.y);
            fma2(a0[6], d0, wD.x); fma2(a0[7], d0, wD.y);
            fma2(a1[0], d1, wA.x); fma2(a1[1], d1, wA.y);
            fma2(a1[2], d1, wB.x); fma2(a1[3], d1, wB.y);
            fma2(a1[4], d1, wC.x); fma2(a1[5], d1, wC.y);
            fma2(a1[6], d1, wD.x); fma2(a1[7], d1, wD.y);
        }
    }
#pragma unroll
    for (int j = 0; j < 8; j++) {
        float2 v0 = unpk(a0[j]);
        float2 v1 = unpk(a1[j]);
        int c0 = 2 * j, c1 = 2 * j + 1;
        float r;
        r = v0.x + sb[c0]; g_h1[(b * 256 + g * 16 + c0) * 400 + p0] = r > 0.f ? r : 0.f;
        r = v0.y + sb[c1]; g_h1[(b * 256 + g * 16 + c1) * 400 + p0] = r > 0.f ? r : 0.f;
        if (has1) {
            r = v1.x + sb[c0]; g_h1[(b * 256 + g * 16 + c0) * 400 + p1] = r > 0.f ? r : 0.f;
            r = v1.y + sb[c1]; g_h1[(b * 256 + g * 16 + c1) * 400 + p1] = r > 0.f ? r : 0.f;
        }
    }
}

// ---------------- primary caps conv via mma.sync (bf16 hi/lo split) + fused squash -----
// grid 256 (2 batches/block), 512 threads (16 warps: 2 M-halves x 8 N-slices of 32 oc).
// A: [128 rows][64 k] bf16 as b32 words, row stride 33 words (bank-conflict pad).
// B: [32 kp][260 n] b32 words (k-pair packed), stride 260 (pad).
#define AS 33
#define A_WORDS (128 * AS)             // 4224 words per hi/lo tile
#define BS 260
#define B_WORDS (32 * BS)              // 8320 words per hi/lo tile
#define OFF_BH (2 * A_WORDS * 4)       // 33792 bytes
#define OFF_BL (OFF_BH + B_WORDS * 4)  // 67072
#define PBUF (OFF_BL + B_WORDS * 4)    // 100352 bytes per buffer
#define PRIM_SMEM (2 * PBUF)           // 200704

extern __shared__ char psmem[];

__device__ __forceinline__ void prim_loadB(int buf, int icp, int tid) {
    char* dst = psmem + buf * PBUF + OFF_BH;
    const char* src = (const char*)&g_Bp[icp * 16640];
    for (int i = tid; i < 4160; i += 512) cp16(dst + i * 16, src + i * 16);
}

__device__ __forceinline__ void prim_buildA(int buf, int icp, int tid, int b0) {
    uint32_t* ah = (uint32_t*)(psmem + buf * PBUF);
    uint32_t* al = ah + A_WORDS;
#pragma unroll
    for (int it = 0; it < 2; it++) {
        int t = tid + it * 512;          // 0..1023
        int r = t >> 3, cg = t & 7;      // row 0..127, col-group (8 bf16) 0..7
        int batch = r >> 6, pos = r & 63;
        int y = pos >> 3, x = pos & 7;
        const float* src = &g_h1[((size_t)(b0 + batch) * 256 + icp * 2) * 400 +
                                 2 * y * 20 + 2 * x];
        uint32_t hw[4], lw[4];
#pragma unroll
        for (int jp = 0; jp < 4; jp++) {
            unsigned short hh[2], ll[2];
#pragma unroll
            for (int h = 0; h < 2; h++) {
                int c = cg * 8 + jp * 2 + h;
                int sel = c >> 5, kk = c & 31;
                float v = 0.f;
                if (kk < 25) {
                    int kh = kk / 5, kw = kk - kh * 5;
                    v = __ldg(src + sel * 400 + kh * 20 + kw);
                }
                __nv_bfloat16 hb = __float2bfloat16(v);
                __nv_bfloat16 lb = __float2bfloat16(v - __bfloat162float(hb));
                hh[h] = __bfloat16_as_ushort(hb);
                ll[h] = __bfloat16_as_ushort(lb);
            }
            hw[jp] = (uint32_t)hh[0] | ((uint32_t)hh[1] << 16);
            lw[jp] = (uint32_t)ll[0] | ((uint32_t)ll[1] << 16);
        }
        int base = r * AS + cg * 4;
#pragma unroll
        for (int j = 0; j < 4; j++) { ah[base + j] = hw[j]; al[base + j] = lw[j]; }
    }
}

__global__ __launch_bounds__(512, 1) void prim_mma_kernel(const float* __restrict__ prim_bias) {
    int tid = threadIdx.x;
    int b0 = blockIdx.x * 2;
    int wid = tid >> 5, lane = tid & 31;
    int g = lane >> 2, c = lane & 3;
    int warpM = wid & 1;       // 0/1 -> rows 0-63 / 64-127
    int warpN = wid >> 1;      // 0..7 -> oc slice of 32

    // prologue: buffer 0
    prim_loadB(0, 0, tid);
    cp_commit();
    prim_buildA(0, 0, tid, b0);
    cp_wait0();
    __syncthreads();

    float acc[4][4][4];
#pragma unroll
    for (int mt = 0; mt < 4; mt++)
#pragma unroll
        for (int nt = 0; nt < 4; nt++)
#pragma unroll
            for (int j = 0; j < 4; j++) acc[mt][nt][j] = 0.f;

    for (int icp = 0; icp < 128; icp++) {
        int buf = icp & 1;
        if (icp + 1 < 128) {
            prim_loadB(buf ^ 1, icp + 1, tid);
            cp_commit();
        }
        const uint32_t* Ah = (const uint32_t*)(psmem + buf * PBUF);
        const uint32_t* Al = Ah + A_WORDS;
        const uint32_t* Bh = (const uint32_t*)(psmem + buf * PBUF + OFF_BH);
        const uint32_t* Bl = Bh + B_WORDS;
#pragma unroll
        for (int s = 0; s < 4; s++) {
            uint32_t bh[4][2], bl[4][2];
#pragma unroll
            for (int nt = 0; nt < 4; nt++) {
                int n = warpN * 32 + nt * 8 + g;
                bh[nt][0] = Bh[(8 * s + c) * BS + n];
                bh[nt][1] = Bh[(8 * s + 4 + c) * BS + n];
                bl[nt][0] = Bl[(8 * s + c) * BS + n];
                bl[nt][1] = Bl[(8 * s + 4 + c) * BS + n];
            }
#pragma unroll
            for (int mt = 0; mt < 4; mt++) {
                int row = warpM * 64 + mt * 16 + g;
                const uint32_t* ar = Ah + row * AS + 8 * s + c;
                uint32_t a0 = ar[0], a1 = ar[8 * AS], a2 = ar[4], a3 = ar[8 * AS + 4];
                const uint32_t* lr = Al + row * AS + 8 * s + c;
                uint32_t l0 = lr[0], l1 = lr[8 * AS], l2 = lr[4], l3 = lr[8 * AS + 4];
#pragma unroll
                for (int nt = 0; nt < 4; nt++) {
                    mma_bf16(acc[mt][nt], a0, a1, a2, a3, bh[nt][0], bh[nt][1]);
                    mma_bf16(acc[mt][nt], a0, a1, a2, a3, bl[nt][0], bl[nt][1]);
                    mma_bf16(acc[mt][nt], l0, l1, l2, l3, bh[nt][0], bh[nt][1]);
                }
            }
        }
        if (icp + 1 < 128) {
            prim_buildA(buf ^ 1, icp + 1, tid, b0);
            cp_wait0();
        }
        __syncthreads();
    }

    // fused epilogue: route=1/32, +bias, squash over the 8 atoms of each capsule.
    // Thread holds atoms {2c, 2c+1}; quad (lanes sharing g) holds all 8 -> shfl.bfly.
    int b_ = b0 + warpM;
#pragma unroll
    for (int mt = 0; mt < 4; mt++) {
        int pos1 = mt * 16 + g;        // rows warpM*64 + mt*16 + g
        int pos2 = pos1 + 8;
#pragma unroll
        for (int nt = 0; nt < 4; nt++) {
            int caps = warpN * 4 + nt;
            float bv0 = __ldg(&prim_bias[caps * 8 + 2 * c]);
            float bv1 = __ldg(&prim_bias[caps * 8 + 2 * c + 1]);
            float v0 = acc[mt][nt][0] * (1.f / 32.f) + bv0;
            float v1 = acc[mt][nt][1] * (1.f / 32.f) + bv1;
            float v2 = acc[mt][nt][2] * (1.f / 32.f) + bv0;
            float v3 = acc[mt][nt][3] * (1.f / 32.f) + bv1;
            float na = v0 * v0 + v1 * v1;
            float nb = v2 * v2 + v3 * v3;
            na += __shfl_xor_sync(0xFFFFFFFFu, na, 1);
            na += __shfl_xor_sync(0xFFFFFFFFu, na, 2);
            nb += __shfl_xor_sync(0xFFFFFFFFu, nb, 1);
            nb += __shfl_xor_sync(0xFFFFFFFFu, nb, 2);
            float fa = (na / (1.f + na)) * rsqrtf(na + 1e-8f);
            float fb = (nb / (1.f + nb)) * rsqrtf(nb + 1e-8f);
            size_t base = ((size_t)(b_ * 32 + caps) * 8) * 64;
            g_p[base + (2 * c) * 64 + pos1] = v0 * fa;
            g_p[base + (2 * c + 1) * 64 + pos1] = v1 * fa;
            g_p[base + (2 * c) * 64 + pos2] = v2 * fb;
            g_p[base + (2 * c + 1) * 64 + pos2] = v3 * fb;
        }
    }
}

// ---------------- conv-caps votes (f32x2) ----------------
__global__ __launch_bounds__(256) void cc_votes_kernel() {
    extern __shared__ float smem[];
    float* sp = smem;
    float* swc = smem + 16384;
    int b = blockIdx.x, tid = threadIdx.x;
    for (int idx = tid; idx < 16384; idx += 256) sp[idx] = g_p[b * 16384 + idx];

    int ocg = tid & 7;
    int i = tid >> 3;
    for (int occ = 0; occ < 4; occ++) {
        __syncthreads();
        for (int idx = tid; idx < 12800; idx += 256)
            swc[idx] = g_cwT[(idx >> 6) * 256 + occ * 64 + (idx & 63)];
        __syncthreads();
        unsigned long long acc[4][4];
#pragma unroll
        for (int p = 0; p < 4; p++)
#pragma unroll
            for (int j = 0; j < 4; j++) acc[p][j] = 0ULL;
#pragma unroll
        for (int cc = 0; cc < 8; cc++) {
            const float* spc = &sp[(i * 8 + cc) * 64];
#pragma unroll
            for (int kh = 0; kh < 5; kh++) {
#pragma unroll
                for (int kw = 0; kw < 5; kw++) {
                    unsigned long long d00 = bcast2(spc[kh * 8 + kw]);
                    unsigned long long d01 = bcast2(spc[kh * 8 + kw + 2]);
                    unsigned long long d10 = bcast2(spc[(kh + 2) * 8 + kw]);
                    unsigned long long d11 = bcast2(spc[(kh + 2) * 8 + kw + 2]);
                    const ulonglong2* wp =
                        (const ulonglong2*)&swc[(cc * 25 + kh * 5 + kw) * 64 + ocg * 8];
                    ulonglong2 wA = wp[0], wB = wp[1];
                    fma2(acc[0][0], d00, wA.x); fma2(acc[0][1], d00, wA.y);
                    fma2(acc[0][2], d00, wB.x); fma2(acc[0][3], d00, wB.y);
                    fma2(acc[1][0], d01, wA.x); fma2(acc[1][1], d01, wA.y);
                    fma2(acc[1][2], d01, wB.x); fma2(acc[1][3], d01, wB.y);
                    fma2(acc[2][0], d10, wA.x); fma2(acc[2][1], d10, wA.y);
                    fma2(acc[2][2], d10, wB.x); fma2(acc[2][3], d10, wB.y);
                    fma2(acc[3][0], d11, wA.x); fma2(acc[3][1], d11, wA.y);
                    fma2(acc[3][2], d11, wB.x); fma2(acc[3][3], d11, wB.y);
                }
            }
        }
#pragma unroll
        for (int p = 0; p < 4; p++) {
            float2 q0 = unpk(acc[p][0]), q1 = unpk(acc[p][1]);
            float2 q2 = unpk(acc[p][2]), q3 = unpk(acc[p][3]);
            float4* dst = (float4*)&g_votes2[((b * 4 + p) * 32 + i) * 256 + occ * 64 + ocg * 8];
            dst[0] = make_float4(q0.x, q0.y, q1.x, q1.y);
            dst[1] = make_float4(q2.x, q2.y, q3.x, q3.y);
        }
    }
}

// ---------------- conv-caps routing (3 iters) ----------------
__global__ __launch_bounds__(256) void cc_routing_kernel(const float* __restrict__ conv_bias) {
    __shared__ float sv[8192];
    __shared__ float slog[1024];
    __shared__ float sroute[1024];
    __shared__ float spre[256];
    __shared__ float sact[256];
    int blk = blockIdx.x;
    int b = blk >> 2, pos = blk & 3;
    int tid = threadIdx.x;
    for (int idx = tid; idx < 8192; idx += 256)
        sv[idx] = g_votes2[(b * 4 + pos) * 8192 + idx];
    for (int e = tid; e < 1024; e += 256) slog[e] = 0.f;
    __syncthreads();

    for (int it = 0; it < 3; it++) {
        if (tid < 32) {
            int i = tid;
            float m = slog[i * 32];
            for (int o = 1; o < 32; o++) m = fmaxf(m, slog[i * 32 + o]);
            float z = 0.f;
            for (int o = 0; o < 32; o++) {
                float e = expf(slog[i * 32 + o] - m);
                sroute[i * 32 + o] = e;
                z += e;
            }
            float inv = 1.f / z;
            for (int o = 0; o < 32; o++) sroute[i * 32 + o] *= inv;
        }
        __syncthreads();
        {
            int o = tid >> 3, a = tid & 7;
            float s = conv_bias[o * 8 + a];
            for (int i = 0; i < 32; i++)
                s += sroute[i * 32 + o] * sv[(i * 32 + o) * 8 + a];
            spre[tid] = s;
        }
        __syncthreads();
        {
            int o = tid >> 3;
            float n2 = 0.f;
#pragma unroll
            for (int a = 0; a < 8; a++) { float v = spre[o * 8 + a]; n2 += v * v; }
            float f = (n2 / (1.f + n2)) * rsqrtf(n2 + 1e-8f);
            sact[tid] = spre[tid] * f;
        }
        __syncthreads();
        if (it < 2) {
            for (int e = tid; e < 1024; e += 256) {
                int o = e & 31;
                float d = 0.f;
#pragma unroll
                for (int a = 0; a < 8; a++) d += sv[e * 8 + a] * sact[o * 8 + a];
                slog[e] += d;
            }
            __syncthreads();
        }
    }
    {
        int o = tid >> 3, a = tid & 7;
        g_c[((b * 32 + o) * 8 + a) * 4 + pos] = sact[tid];
    }
}

// ---------------- digit caps: votes + routing + mask ----------------
__global__ __launch_bounds__(256) void digit_kernel(
    const float* __restrict__ digit_w, const float* __restrict__ digit_bias,
    const float* __restrict__ y, float* __restrict__ out_dcap) {
    __shared__ float smem[11264];
    float* sc = smem;
    float* sdw = smem + 1024;
    float* sv = smem + 6144;
    int b = blockIdx.x, tid = threadIdx.x;
    for (int idx = tid; idx < 1024; idx += 256) sc[idx] = g_c[b * 1024 + idx];
    for (int idx = tid; idx < 5120; idx += 256) sdw[idx] = digit_w[idx];
    __syncthreads();
    for (int idx = tid; idx < 5120; idx += 256) {
        int i = idx / 160, oa = idx % 160;
        float s = 0.f;
        const float* ci = &sc[i * 32];
        const float* wv = &sdw[oa * 32];
#pragma unroll
        for (int z = 0; z < 32; z++) s += ci[z] * wv[z];
        sv[(i * 10 + (oa >> 4)) * 16 + (oa & 15)] = s;
    }
    __syncthreads();
    float* slog = smem;
    float* sroute = smem + 320;
    float* spre = smem + 640;
    float* sact = smem + 800;
    float* sbias = smem + 960;
    for (int e = tid; e < 320; e += 256) slog[e] = 0.f;
    if (tid < 160) sbias[tid] = digit_bias[tid];
    __syncthreads();

    for (int it = 0; it < 3; it++) {
        if (tid < 32) {
            int i = tid;
            float m = slog[i * 10];
            for (int o = 1; o < 10; o++) m = fmaxf(m, slog[i * 10 + o]);
            float z = 0.f;
            for (int o = 0; o < 10; o++) {
                float e = expf(slog[i * 10 + o] - m);
                sroute[i * 10 + o] = e;
                z += e;
            }
            float inv = 1.f / z;
            for (int o = 0; o < 10; o++) sroute[i * 10 + o] *= inv;
        }
        __syncthreads();
        if (tid < 160) {
            int o = tid >> 4, a = tid & 15;
            float s = sbias[tid];
            for (int i = 0; i < 32; i++)
                s += sroute[i * 10 + o] * sv[(i * 10 + o) * 16 + a];
            spre[tid] = s;
        }
        __syncthreads();
        if (tid < 160) {
            int o = tid >> 4;
            float n2 = 0.f;
#pragma unroll
            for (int a = 0; a < 16; a++) { float v = spre[o * 16 + a]; n2 += v * v; }
            float f = (n2 / (1.f + n2)) * rsqrtf(n2 + 1e-8f);
            sact[tid] = spre[tid] * f;
        }
        __syncthreads();
        if (it < 2) {
            for (int e = tid; e < 320; e += 256) {
                int o = e % 10;
                float d = 0.f;
#pragma unroll
                for (int a = 0; a < 16; a++) d += sv[e * 16 + a] * sact[o * 16 + a];
                slog[e] += d;
            }
            __syncthreads();
        }
    }
    if (tid < 160) {
        int o = tid >> 4;
        float v = sact[tid];
        out_dcap[b * 160 + tid] = v;
        g_masked[b * 160 + tid] = v * y[b * 10 + o];
    }
}

// ---------------- FC: C = act(A @ W + bias) ----------------
template <int ACT>
__global__ __launch_bounds__(256) void fc_kernel(
    const float* __restrict__ A, const float* __restrict__ W,
    const float* __restrict__ bias, float* __restrict__ C,
    int M, int K, int N) {
    __shared__ float As[16][64];
    __shared__ float Ws[16][64];
    int m0 = blockIdx.y * 64, n0 = blockIdx.x * 64;
    int tid = threadIdx.x;
    int tr = tid >> 4, tc = tid & 15;
    float acc[4][4];
#pragma unroll
    for (int i = 0; i < 4; i++)
#pragma unroll
        for (int j = 0; j < 4; j++) acc[i][j] = 0.f;

    for (int k0 = 0; k0 < K; k0 += 16) {
        for (int l = tid; l < 1024; l += 256) {
            int ml = l >> 4, kl = l & 15;
            As[kl][ml] = A[(m0 + ml) * K + k0 + kl];
        }
        for (int l = tid; l < 1024; l += 256) {
            int kl = l >> 6, nl = l & 63;
            int n = n0 + nl;
            Ws[kl][nl] = (n < N) ? W[(k0 + kl) * N + n] : 0.f;
        }
        __syncthreads();
#pragma unroll
        for (int kk = 0; kk < 16; kk++) {
            float4 a4 = *(const float4*)&As[kk][tr * 4];
            float4 b4 = *(const float4*)&Ws[kk][tc * 4];
            float av[4] = {a4.x, a4.y, a4.z, a4.w};
            float bv[4] = {b4.x, b4.y, b4.z, b4.w};
#pragma unroll
            for (int i = 0; i < 4; i++)
#pragma unroll
                for (int j = 0; j < 4; j++) acc[i][j] += av[i] * bv[j];
        }
        __syncthreads();
    }
#pragma unroll
    for (int i = 0; i < 4; i++) {
        int m = m0 + tr * 4 + i;
#pragma unroll
        for (int j = 0; j < 4; j++) {
            int n = n0 + tc * 4 + j;
            if (n < N) {
                float v = acc[i][j] + bias[n];
                if (ACT == 1) v = v > 0.f ? v : 0.f;
                if (ACT == 2) v = 1.f / (1.f + expf(-v));
                C[m * N + n] = v;
            }
        }
    }
}

// ---------------- launcher ----------------
extern "C" void kernel_launch(void* const* d_in, const int* in_sizes, int n_in,
                              void* d_out, int out_size) {
    const float* x = (const float*)d_in[0];
    const float* y = (const float*)d_in[1];
    const float* conv1_w = (const float*)d_in[2];
    const float* conv1_b = (const float*)d_in[3];
    const float* prim_w = (const float*)d_in[4];
    const float* prim_bias = (const float*)d_in[5];
    const float* conv_w = (const float*)d_in[6];
    const float* conv_bias = (const float*)d_in[7];
    const float* digit_w = (const float*)d_in[8];
    const float* digit_bias = (const float*)d_in[9];
    const float* fc1_w = (const float*)d_in[10];
    const float* fc1_b = (const float*)d_in[11];
    const float* fc2_w = (const float*)d_in[12];
    const float* fc2_b = (const float*)d_in[13];
    const float* fc3_w = (const float*)d_in[14];
    const float* fc3_b = (const float*)d_in[15];
    float* out = (float*)d_out;              // [0:81920) dcap, [81920:483328) recon

    static float *p_masked = nullptr, *p_r1 = nullptr, *p_r2 = nullptr;
    static float *g_cwT_p = nullptr;
    static bool attrs_set = false;
    if (!p_masked) {
        cudaGetSymbolAddress((void**)&p_masked, g_masked);
        cudaGetSymbolAddress((void**)&p_r1, g_r1);
        cudaGetSymbolAddress((void**)&p_r2, g_r2);
        cudaGetSymbolAddress((void**)&g_cwT_p, g_cwT);
    }
    if (!attrs_set) {
        cudaFuncSetAttribute(prim_mma_kernel, cudaFuncAttributeMaxDynamicSharedMemorySize,
                             PRIM_SMEM);
        cudaFuncSetAttribute(cc_votes_kernel, cudaFuncAttributeMaxDynamicSharedMemorySize,
                             (16384 + 12800) * 4);
        attrs_set = true;
    }

    // weight prep
    prepack_B<<<(128 * 2 * 8320 + 255) / 256, 256>>>(prim_w);
    transpose_oc<<<200, 256>>>(conv_w, g_cwT_p, 256, 200);

    // conv1 + relu
    conv1_kernel<<<dim3(512, 16), 256>>>(x, conv1_w, conv1_b);

    // primary caps conv via mma.sync tensor cores + fused squash
    prim_mma_kernel<<<256, 512, PRIM_SMEM>>>(prim_bias);

    // conv caps votes
    cc_votes_kernel<<<512, 256, (16384 + 12800) * 4>>>();

    // conv caps routing
    cc_routing_kernel<<<2048, 256>>>(conv_bias);

    // digit caps
    digit_kernel<<<512, 256>>>(digit_w, digit_bias, y, out);

    // FC reconstruction chain
    fc_kernel<1><<<dim3(8, 8), 256>>>(p_masked, fc1_w, fc1_b, p_r1, 512, 160, 512);
    fc_kernel<1><<<dim3(16, 8), 256>>>(p_r1, fc2_w, fc2_b, p_r2, 512, 512, 1024);
    fc_kernel<2><<<dim3(13, 8), 256>>>(p_r2, fc3_w, fc3_b, out + 81920, 512, 1024, 784);
}

// round 6
// speedup vs baseline: 2.2634x; 1.4164x over previous
#include <cuda_runtime.h>
#include <cuda_bf16.h>
#include <math.h>
#include <stdint.h>

// ---------------- problem constants ----------------
#define BATCH 512
#define NPRIM 32
#define NCLASS 10

// ---------------- scratch (static device memory; no allocs allowed) ----------------
// conv1 output as bf16 hi/lo split, layout [b][pixel(400)][ic(256)]
__device__ __align__(256) unsigned short g_h1h[BATCH * 400 * 256];   // 100 MB
__device__ __align__(256) unsigned short g_h1l[BATCH * 400 * 256];   // 100 MB
// prim weights prepacked: [kpos25][chunk4][oc256][ic64] bf16 hi/lo
__device__ __align__(256) unsigned short g_Wph[25 * 4 * 256 * 64];   // 3.3 MB
__device__ __align__(256) unsigned short g_Wpl[25 * 4 * 256 * 64];   // 3.3 MB
__device__ float g_cwT[8 * 25 * 256];                    // conv_w transposed [c*25+k][oc]
__device__ float g_p[BATCH * NPRIM * 8 * 64];            // primary caps acts [b][i][a][pos]
__device__ float g_votes2[BATCH * 4 * 32 * 256];         // [b][pos][i][oc]
__device__ float g_c[BATCH * 32 * 8 * 4];                // [b][o][a][pos]
__device__ float g_masked[BATCH * 160];
__device__ float g_r1[BATCH * 512];
__device__ float g_r2[BATCH * 1024];

// ---------------- f32x2 helpers ----------------
__device__ __forceinline__ unsigned long long bcast2(float v) {
    unsigned long long r;
    asm("mov.b64 %0, {%1, %1};" : "=l"(r) : "f"(v));
    return r;
}
__device__ __forceinline__ void fma2(unsigned long long& acc, unsigned long long a,
                                     unsigned long long b) {
    asm("fma.rn.f32x2 %0, %1, %2, %0;" : "+l"(acc) : "l"(a), "l"(b));
}
__device__ __forceinline__ float2 unpk(unsigned long long v) {
    float2 r;
    asm("mov.b64 {%0, %1}, %2;" : "=f"(r.x), "=f"(r.y) : "l"(v));
    return r;
}

// ---------------- cp.async helpers ----------------
__device__ __forceinline__ void cp16(void* smem, const void* g) {
    unsigned s;
    asm("{ .reg .u64 t; cvta.to.shared.u64 t, %1; cvt.u32.u64 %0, t; }"
        : "=r"(s) : "l"(smem));
    asm volatile("cp.async.cg.shared.global [%0], [%1], 16;" :: "r"(s), "l"(g));
}
__device__ __forceinline__ void cp_commit() { asm volatile("cp.async.commit_group;"); }
__device__ __forceinline__ void cp_wait0() {
    asm volatile("cp.async.wait_group 0;" ::: "memory");
}
__device__ __forceinline__ void cp_wait1() {
    asm volatile("cp.async.wait_group 1;" ::: "memory");
}

// ---------------- mma.sync bf16 + ldmatrix (sm_80+ legacy tensor path) ----------------
__device__ __forceinline__ void mma_bf16(float* d, const uint32_t* a, uint32_t b0,
                                         uint32_t b1) {
    asm volatile(
        "mma.sync.aligned.m16n8k16.row.col.f32.bf16.bf16.f32 "
        "{%0,%1,%2,%3}, {%4,%5,%6,%7}, {%8,%9}, {%0,%1,%2,%3};"
        : "+f"(d[0]), "+f"(d[1]), "+f"(d[2]), "+f"(d[3])
        : "r"(a[0]), "r"(a[1]), "r"(a[2]), "r"(a[3]), "r"(b0), "r"(b1));
}
__device__ __forceinline__ void ldm_x4(uint32_t* r, uint32_t addr) {
    asm volatile("ldmatrix.sync.aligned.m8n8.x4.shared.b16 {%0,%1,%2,%3}, [%4];"
        : "=r"(r[0]), "=r"(r[1]), "=r"(r[2]), "=r"(r[3]) : "r"(addr));
}
__device__ __forceinline__ uint32_t smem_u32(const void* p) {
    uint32_t a;
    asm("{ .reg .u64 t; cvta.to.shared.u64 t, %1; cvt.u32.u64 %0, t; }" : "=r"(a) : "l"(p));
    return a;
}

// ---------------- weight transpose: w[oc][ick] -> wt[ick][oc] ----------------
__global__ void transpose_oc(const float* __restrict__ w, float* __restrict__ wt,
                             int OC, int ICK) {
    int idx = blockIdx.x * 256 + threadIdx.x;
    if (idx >= OC * ICK) return;
    int ick = idx / OC, oc = idx % OC;
    wt[idx] = w[oc * ICK + ick];
}

// ---------------- prepack prim weights: [kpos][chunk][oc][ic64] bf16 hi/lo ------------
__global__ void prepack_W(const float* __restrict__ w) {
    int idx = blockIdx.x * 256 + threadIdx.x;
    if (idx >= 25 * 4 * 256 * 64) return;
    int ic = idx & 63;
    int oc = (idx >> 6) & 255;
    int chunk = (idx >> 14) & 3;
    int kpos = idx >> 16;
    float v = w[oc * 6400 + (chunk * 64 + ic) * 25 + kpos];
    __nv_bfloat16 hi = __float2bfloat16(v);
    __nv_bfloat16 lo = __float2bfloat16(v - __bfloat162float(hi));
    g_Wph[idx] = __bfloat16_as_ushort(hi);
    g_Wpl[idx] = __bfloat16_as_ushort(lo);
}

// ---------------- conv1 + relu (f32x2), writes bf16 hi/lo [b][pix][ic] ----------------
__global__ __launch_bounds__(256) void conv1_kernel(
    const float* __restrict__ x, const float* __restrict__ w,
    const float* __restrict__ bias) {
    __shared__ float sx[784];
    __shared__ float sw2[81 * 16];
    __shared__ float sb[16];
    int b = blockIdx.x, g = blockIdx.y, tid = threadIdx.x;
    for (int i = tid; i < 784; i += 256) sx[i] = x[b * 784 + i];
    for (int i = tid; i < 81 * 16; i += 256) {
        int k = i >> 4, c = i & 15;
        sw2[i] = w[(g * 16 + c) * 81 + k];
    }
    if (tid < 16) sb[tid] = bias[g * 16 + tid];
    __syncthreads();

    int p0 = tid;
    int p1 = tid + 256;
    bool has1 = (p1 < 400);
    int p1c = has1 ? p1 : 0;
    int y0 = p0 / 20, x0 = p0 % 20;
    int y1 = p1c / 20, x1 = p1c % 20;
    unsigned long long a0[8], a1[8];
#pragma unroll
    for (int j = 0; j < 8; j++) { a0[j] = 0ULL; a1[j] = 0ULL; }
#pragma unroll
    for (int kh = 0; kh < 9; kh++) {
#pragma unroll
        for (int kw = 0; kw < 9; kw++) {
            unsigned long long d0 = bcast2(sx[(y0 + kh) * 28 + x0 + kw]);
            unsigned long long d1 = bcast2(sx[(y1 + kh) * 28 + x1 + kw]);
            int k = kh * 9 + kw;
            const ulonglong2* wp = (const ulonglong2*)&sw2[k * 16];
            ulonglong2 wA = wp[0], wB = wp[1], wC = wp[2], wD = wp[3];
            fma2(a0[0], d0, wA.x); fma2(a0[1], d0, wA.y);
            fma2(a0[2], d0, wB.x); fma2(a0[3], d0, wB.y);
            fma2(a0[4], d0, wC.x); fma2(a0[5], d0, wC.y);
            fma2(a0[6], d0, wD.x); fma2(a0[7], d0, wD.y);
            fma2(a1[0], d1, wA.x); fma2(a1[1], d1, wA.y);
            fma2(a1[2], d1, wB.x); fma2(a1[3], d1, wB.y);
            fma2(a1[4], d1, wC.x); fma2(a1[5], d1, wC.y);
            fma2(a1[6], d1, wD.x); fma2(a1[7], d1, wD.y);
        }
    }
#pragma unroll
    for (int half = 0; half < 2; half++) {
        if (half == 1 && !has1) break;
        int p = half ? p1 : p0;
        unsigned long long* A = half ? a1 : a0;
        uint32_t hw[8], lw[8];
#pragma unroll
        for (int j = 0; j < 8; j++) {
            float2 v = unpk(A[j]);
            float r0 = v.x + sb[2 * j];     r0 = r0 > 0.f ? r0 : 0.f;
            float r1 = v.y + sb[2 * j + 1]; r1 = r1 > 0.f ? r1 : 0.f;
            __nv_bfloat16 h0 = __float2bfloat16(r0);
            __nv_bfloat16 h1 = __float2bfloat16(r1);
            __nv_bfloat16 l0 = __float2bfloat16(r0 - __bfloat162float(h0));
            __nv_bfloat16 l1 = __float2bfloat16(r1 - __bfloat162float(h1));
            hw[j] = (uint32_t)__bfloat16_as_ushort(h0) |
                    ((uint32_t)__bfloat16_as_ushort(h1) << 16);
            lw[j] = (uint32_t)__bfloat16_as_ushort(l0) |
                    ((uint32_t)__bfloat16_as_ushort(l1) << 16);
        }
        size_t base = ((size_t)b * 400 + p) * 256 + g * 16;
        uint4* dh = (uint4*)&g_h1h[base];
        uint4* dl = (uint4*)&g_h1l[base];
        dh[0] = make_uint4(hw[0], hw[1], hw[2], hw[3]);
        dh[1] = make_uint4(hw[4], hw[5], hw[6], hw[7]);
        dl[0] = make_uint4(lw[0], lw[1], lw[2], lw[3]);
        dl[1] = make_uint4(lw[4], lw[5], lw[6], lw[7]);
    }
}

// ---------------- primary caps conv via mma.sync + ldmatrix, K=ic, no im2col ALU ------
// grid 256 (2 batches/block), 512 threads (16 warps: warpM 0/1 x warpN 0..7 of 32 oc).
// 100 k-steps: (kpos 0..24) x (ic chunk 0..3, 64 ic each). A/B tiles pitch 144 B.
#define PITCH 144
#define OFF_AH 0
#define OFF_AL 18432                   // 128*144
#define OFF_BH 36864
#define OFF_BL 73728                   // OFF_BH + 256*144
#define PBUF 110592
#define PRIM_SMEM (2 * PBUF)           // 221184

extern __shared__ char psmem[];

__device__ __forceinline__ void prim_load_step(int buf, int s, int tid, int b0) {
    int kpos = s >> 2, chunk = s & 3;
    int kh = kpos / 5, kw = kpos - kh * 5;
    char* base = psmem + buf * PBUF;
    // A: 128 rows x 128B from g_h1h/g_h1l
#pragma unroll
    for (int ii = 0; ii < 2; ii++) {
        int i = tid + ii * 512;          // 0..1023
        int r = i >> 3, seg = i & 7;
        int batch = r >> 6, pos = r & 63;
        int y = pos >> 3, xx = pos & 7;
        int pix = (2 * y + kh) * 20 + 2 * xx + kw;
        size_t src = ((size_t)(b0 + batch) * 400 + pix) * 256 + chunk * 64 + seg * 8;
        char* d = base + r * PITCH + seg * 16;
        cp16(d + OFF_AH, &g_h1h[src]);
        cp16(d + OFF_AL, &g_h1l[src]);
    }
    // B: 256 rows x 128B from g_Wph/g_Wpl
    size_t wbase = (size_t)s * 16384;    // (kpos*4+chunk)*256*64
#pragma unroll
    for (int ii = 0; ii < 4; ii++) {
        int i = tid + ii * 512;          // 0..2047
        int r = i >> 3, seg = i & 7;
        size_t src = wbase + r * 64 + seg * 8;
        char* d = base + r * PITCH + seg * 16;
        cp16(d + OFF_BH, &g_Wph[src]);
        cp16(d + OFF_BL, &g_Wpl[src]);
    }
}

__global__ __launch_bounds__(512, 1) void prim_mma_kernel(const float* __restrict__ prim_bias) {
    int tid = threadIdx.x;
    int b0 = blockIdx.x * 2;
    int wid = tid >> 5, lane = tid & 31;
    int g = lane >> 2, c = lane & 3;
    int warpM = wid & 1;       // rows 0-63 / 64-127
    int warpN = wid >> 1;      // oc slice of 32

    uint32_t sbase = smem_u32(psmem);
    // ldmatrix lane address components
    uint32_t aOff = (uint32_t)(warpM * 64 + (lane & 15)) * PITCH + ((lane >> 4) << 4);
    uint32_t bRow = (uint32_t)(warpN * 32 + (lane & 7) + ((lane & 16) >> 1));
    uint32_t bOff = bRow * PITCH + ((lane & 8) ? 16u : 0u);

    float acc[4][4][4];
#pragma unroll
    for (int mt = 0; mt < 4; mt++)
#pragma unroll
        for (int j = 0; j < 4; j++)
#pragma unroll
            for (int q = 0; q < 4; q++) acc[mt][j][q] = 0.f;

    prim_load_step(0, 0, tid, b0);
    cp_commit();

    for (int s = 0; s < 100; s++) {
        int buf = s & 1;
        if (s + 1 < 100) {
            prim_load_step(buf ^ 1, s + 1, tid, b0);
            cp_commit();
            cp_wait1();
        } else {
            cp_wait0();
        }
        __syncthreads();

        uint32_t tbase = sbase + buf * PBUF;
        uint32_t aBase = tbase + OFF_AH + aOff;
        uint32_t bBase = tbase + OFF_BH + bOff;
#pragma unroll
        for (int kk = 0; kk < 4; kk++) {
            uint32_t bh[2][4], bl[2][4];
#pragma unroll
            for (int np = 0; np < 2; np++) {
                ldm_x4(bh[np], bBase + np * (16 * PITCH) + kk * 32);
                ldm_x4(bl[np], bBase + (OFF_BL - OFF_BH) + np * (16 * PITCH) + kk * 32);
            }
#pragma unroll
            for (int mt = 0; mt < 4; mt++) {
                uint32_t ah[4], al[4];
                ldm_x4(ah, aBase + mt * (16 * PITCH) + kk * 32);
                ldm_x4(al, aBase + (OFF_AL - OFF_AH) + mt * (16 * PITCH) + kk * 32);
#pragma unroll
                for (int np = 0; np < 2; np++)
#pragma unroll
                    for (int nt = 0; nt < 2; nt++) {
                        float* d = acc[mt][np * 2 + nt];
                        mma_bf16(d, ah, bh[np][nt * 2], bh[np][nt * 2 + 1]);
                        mma_bf16(d, ah, bl[np][nt * 2], bl[np][nt * 2 + 1]);
                        mma_bf16(d, al, bh[np][nt * 2], bh[np][nt * 2 + 1]);
                    }
            }
        }
        __syncthreads();
    }

    // fused epilogue: route=1/32, +bias, squash over 8 atoms (quad shfl reduction)
    int b_ = b0 + warpM;
#pragma unroll
    for (int mt = 0; mt < 4; mt++) {
        int pos1 = mt * 16 + g;
        int pos2 = pos1 + 8;
#pragma unroll
        for (int j = 0; j < 4; j++) {
            int caps = warpN * 4 + j;
            float bv0 = __ldg(&prim_bias[caps * 8 + 2 * c]);
            float bv1 = __ldg(&prim_bias[caps * 8 + 2 * c + 1]);
            float v0 = acc[mt][j][0] * (1.f / 32.f) + bv0;
            float v1 = acc[mt][j][1] * (1.f / 32.f) + bv1;
            float v2 = acc[mt][j][2] * (1.f / 32.f) + bv0;
            float v3 = acc[mt][j][3] * (1.f / 32.f) + bv1;
            float na = v0 * v0 + v1 * v1;
            float nb = v2 * v2 + v3 * v3;
            na += __shfl_xor_sync(0xFFFFFFFFu, na, 1);
            na += __shfl_xor_sync(0xFFFFFFFFu, na, 2);
            nb += __shfl_xor_sync(0xFFFFFFFFu, nb, 1);
            nb += __shfl_xor_sync(0xFFFFFFFFu, nb, 2);
            float fa = (na / (1.f + na)) * rsqrtf(na + 1e-8f);
            float fb = (nb / (1.f + nb)) * rsqrtf(nb + 1e-8f);
            size_t base = ((size_t)(b_ * 32 + caps) * 8) * 64;
            g_p[base + (2 * c) * 64 + pos1] = v0 * fa;
            g_p[base + (2 * c + 1) * 64 + pos1] = v1 * fa;
            g_p[base + (2 * c) * 64 + pos2] = v2 * fb;
            g_p[base + (2 * c + 1) * 64 + pos2] = v3 * fb;
        }
    }
}

// ---------------- conv-caps votes (f32x2) ----------------
__global__ __launch_bounds__(256) void cc_votes_kernel() {
    extern __shared__ float smem[];
    float* sp = smem;
    float* swc = smem + 16384;
    int b = blockIdx.x, tid = threadIdx.x;
    for (int idx = tid; idx < 16384; idx += 256) sp[idx] = g_p[b * 16384 + idx];

    int ocg = tid & 7;
    int i = tid >> 3;
    for (int occ = 0; occ < 4; occ++) {
        __syncthreads();
        for (int idx = tid; idx < 12800; idx += 256)
            swc[idx] = g_cwT[(idx >> 6) * 256 + occ * 64 + (idx & 63)];
        __syncthreads();
        unsigned long long acc[4][4];
#pragma unroll
        for (int p = 0; p < 4; p++)
#pragma unroll
            for (int j = 0; j < 4; j++) acc[p][j] = 0ULL;
#pragma unroll
        for (int cc = 0; cc < 8; cc++) {
            const float* spc = &sp[(i * 8 + cc) * 64];
#pragma unroll
            for (int kh = 0; kh < 5; kh++) {
#pragma unroll
                for (int kw = 0; kw < 5; kw++) {
                    unsigned long long d00 = bcast2(spc[kh * 8 + kw]);
                    unsigned long long d01 = bcast2(spc[kh * 8 + kw + 2]);
                    unsigned long long d10 = bcast2(spc[(kh + 2) * 8 + kw]);
                    unsigned long long d11 = bcast2(spc[(kh + 2) * 8 + kw + 2]);
                    const ulonglong2* wp =
                        (const ulonglong2*)&swc[(cc * 25 + kh * 5 + kw) * 64 + ocg * 8];
                    ulonglong2 wA = wp[0], wB = wp[1];
                    fma2(acc[0][0], d00, wA.x); fma2(acc[0][1], d00, wA.y);
                    fma2(acc[0][2], d00, wB.x); fma2(acc[0][3], d00, wB.y);
                    fma2(acc[1][0], d01, wA.x); fma2(acc[1][1], d01, wA.y);
                    fma2(acc[1][2], d01, wB.x); fma2(acc[1][3], d01, wB.y);
                    fma2(acc[2][0], d10, wA.x); fma2(acc[2][1], d10, wA.y);
                    fma2(acc[2][2], d10, wB.x); fma2(acc[2][3], d10, wB.y);
                    fma2(acc[3][0], d11, wA.x); fma2(acc[3][1], d11, wA.y);
                    fma2(acc[3][2], d11, wB.x); fma2(acc[3][3], d11, wB.y);
                }
            }
        }
#pragma unroll
        for (int p = 0; p < 4; p++) {
            float2 q0 = unpk(acc[p][0]), q1 = unpk(acc[p][1]);
            float2 q2 = unpk(acc[p][2]), q3 = unpk(acc[p][3]);
            float4* dst = (float4*)&g_votes2[((b * 4 + p) * 32 + i) * 256 + occ * 64 + ocg * 8];
            dst[0] = make_float4(q0.x, q0.y, q1.x, q1.y);
            dst[1] = make_float4(q2.x, q2.y, q3.x, q3.y);
        }
    }
}

// ---------------- conv-caps routing (3 iters) ----------------
__global__ __launch_bounds__(256) void cc_routing_kernel(const float* __restrict__ conv_bias) {
    __shared__ float sv[8192];
    __shared__ float slog[1024];
    __shared__ float sroute[1024];
    __shared__ float spre[256];
    __shared__ float sact[256];
    int blk = blockIdx.x;
    int b = blk >> 2, pos = blk & 3;
    int tid = threadIdx.x;
    for (int idx = tid; idx < 8192; idx += 256)
        sv[idx] = g_votes2[(b * 4 + pos) * 8192 + idx];
    for (int e = tid; e < 1024; e += 256) slog[e] = 0.f;
    __syncthreads();

    for (int it = 0; it < 3; it++) {
        if (tid < 32) {
            int i = tid;
            float m = slog[i * 32];
            for (int o = 1; o < 32; o++) m = fmaxf(m, slog[i * 32 + o]);
            float z = 0.f;
            for (int o = 0; o < 32; o++) {
                float e = expf(slog[i * 32 + o] - m);
                sroute[i * 32 + o] = e;
                z += e;
            }
            float inv = 1.f / z;
            for (int o = 0; o < 32; o++) sroute[i * 32 + o] *= inv;
        }
        __syncthreads();
        {
            int o = tid >> 3, a = tid & 7;
            float s = conv_bias[o * 8 + a];
            for (int i = 0; i < 32; i++)
                s += sroute[i * 32 + o] * sv[(i * 32 + o) * 8 + a];
            spre[tid] = s;
        }
        __syncthreads();
        {
            int o = tid >> 3;
            float n2 = 0.f;
#pragma unroll
            for (int a = 0; a < 8; a++) { float v = spre[o * 8 + a]; n2 += v * v; }
            float f = (n2 / (1.f + n2)) * rsqrtf(n2 + 1e-8f);
            sact[tid] = spre[tid] * f;
        }
        __syncthreads();
        if (it < 2) {
            for (int e = tid; e < 1024; e += 256) {
                int o = e & 31;
                float d = 0.f;
#pragma unroll
                for (int a = 0; a < 8; a++) d += sv[e * 8 + a] * sact[o * 8 + a];
                slog[e] += d;
            }
            __syncthreads();
        }
    }
    {
        int o = tid >> 3, a = tid & 7;
        g_c[((b * 32 + o) * 8 + a) * 4 + pos] = sact[tid];
    }
}

// ---------------- digit caps: votes + routing + mask ----------------
__global__ __launch_bounds__(256) void digit_kernel(
    const float* __restrict__ digit_w, const float* __restrict__ digit_bias,
    const float* __restrict__ y, float* __restrict__ out_dcap) {
    __shared__ float smem[11264];
    float* sc = smem;
    float* sdw = smem + 1024;
    float* sv = smem + 6144;
    int b = blockIdx.x, tid = threadIdx.x;
    for (int idx = tid; idx < 1024; idx += 256) sc[idx] = g_c[b * 1024 + idx];
    for (int idx = tid; idx < 5120; idx += 256) sdw[idx] = digit_w[idx];
    __syncthreads();
    for (int idx = tid; idx < 5120; idx += 256) {
        int i = idx / 160, oa = idx % 160;
        float s = 0.f;
        const float* ci = &sc[i * 32];
        const float* wv = &sdw[oa * 32];
#pragma unroll
        for (int z = 0; z < 32; z++) s += ci[z] * wv[z];
        sv[(i * 10 + (oa >> 4)) * 16 + (oa & 15)] = s;
    }
    __syncthreads();
    float* slog = smem;
    float* sroute = smem + 320;
    float* spre = smem + 640;
    float* sact = smem + 800;
    float* sbias = smem + 960;
    for (int e = tid; e < 320; e += 256) slog[e] = 0.f;
    if (tid < 160) sbias[tid] = digit_bias[tid];
    __syncthreads();

    for (int it = 0; it < 3; it++) {
        if (tid < 32) {
            int i = tid;
            float m = slog[i * 10];
            for (int o = 1; o < 10; o++) m = fmaxf(m, slog[i * 10 + o]);
            float z = 0.f;
            for (int o = 0; o < 10; o++) {
                float e = expf(slog[i * 10 + o] - m);
                sroute[i * 10 + o] = e;
                z += e;
            }
            float inv = 1.f / z;
            for (int o = 0; o < 10; o++) sroute[i * 10 + o] *= inv;
        }
        __syncthreads();
        if (tid < 160) {
            int o = tid >> 4, a = tid & 15;
            float s = sbias[tid];
            for (int i = 0; i < 32; i++)
                s += sroute[i * 10 + o] * sv[(i * 10 + o) * 16 + a];
            spre[tid] = s;
        }
        __syncthreads();
        if (tid < 160) {
            int o = tid >> 4;
            float n2 = 0.f;
#pragma unroll
            for (int a = 0; a < 16; a++) { float v = spre[o * 16 + a]; n2 += v * v; }
            float f = (n2 / (1.f + n2)) * rsqrtf(n2 + 1e-8f);
            sact[tid] = spre[tid] * f;
        }
        __syncthreads();
        if (it < 2) {
            for (int e = tid; e < 320; e += 256) {
                int o = e % 10;
                float d = 0.f;
#pragma unroll
                for (int a = 0; a < 16; a++) d += sv[e * 16 + a] * sact[o * 16 + a];
                slog[e] += d;
            }
            __syncthreads();
        }
    }
    if (tid < 160) {
        int o = tid >> 4;
        float v = sact[tid];
        out_dcap[b * 160 + tid] = v;
        g_masked[b * 160 + tid] = v * y[b * 10 + o];
    }
}

// ---------------- FC: C = act(A @ W + bias) ----------------
template <int ACT>
__global__ __launch_bounds__(256) void fc_kernel(
    const float* __restrict__ A, const float* __restrict__ W,
    const float* __restrict__ bias, float* __restrict__ C,
    int M, int K, int N) {
    __shared__ float As[16][64];
    __shared__ float Ws[16][64];
    int m0 = blockIdx.y * 64, n0 = blockIdx.x * 64;
    int tid = threadIdx.x;
    int tr = tid >> 4, tc = tid & 15;
    float acc[4][4];
#pragma unroll
    for (int i = 0; i < 4; i++)
#pragma unroll
        for (int j = 0; j < 4; j++) acc[i][j] = 0.f;

    for (int k0 = 0; k0 < K; k0 += 16) {
        for (int l = tid; l < 1024; l += 256) {
            int ml = l >> 4, kl = l & 15;
            As[kl][ml] = A[(m0 + ml) * K + k0 + kl];
        }
        for (int l = tid; l < 1024; l += 256) {
            int kl = l >> 6, nl = l & 63;
            int n = n0 + nl;
            Ws[kl][nl] = (n < N) ? W[(k0 + kl) * N + n] : 0.f;
        }
        __syncthreads();
#pragma unroll
        for (int kk = 0; kk < 16; kk++) {
            float4 a4 = *(const float4*)&As[kk][tr * 4];
            float4 b4 = *(const float4*)&Ws[kk][tc * 4];
            float av[4] = {a4.x, a4.y, a4.z, a4.w};
            float bv[4] = {b4.x, b4.y, b4.z, b4.w};
#pragma unroll
            for (int i = 0; i < 4; i++)
#pragma unroll
                for (int j = 0; j < 4; j++) acc[i][j] += av[i] * bv[j];
        }
        __syncthreads();
    }
#pragma unroll
    for (int i = 0; i < 4; i++) {
        int m = m0 + tr * 4 + i;
#pragma unroll
        for (int j = 0; j < 4; j++) {
            int n = n0 + tc * 4 + j;
            if (n < N) {
                float v = acc[i][j] + bias[n];
                if (ACT == 1) v = v > 0.f ? v : 0.f;
                if (ACT == 2) v = 1.f / (1.f + expf(-v));
                C[m * N + n] = v;
            }
        }
    }
}

// ---------------- launcher ----------------
extern "C" void kernel_launch(void* const* d_in, const int* in_sizes, int n_in,
                              void* d_out, int out_size) {
    const float* x = (const float*)d_in[0];
    const float* y = (const float*)d_in[1];
    const float* conv1_w = (const float*)d_in[2];
    const float* conv1_b = (const float*)d_in[3];
    const float* prim_w = (const float*)d_in[4];
    const float* prim_bias = (const float*)d_in[5];
    const float* conv_w = (const float*)d_in[6];
    const float* conv_bias = (const float*)d_in[7];
    const float* digit_w = (const float*)d_in[8];
    const float* digit_bias = (const float*)d_in[9];
    const float* fc1_w = (const float*)d_in[10];
    const float* fc1_b = (const float*)d_in[11];
    const float* fc2_w = (const float*)d_in[12];
    const float* fc2_b = (const float*)d_in[13];
    const float* fc3_w = (const float*)d_in[14];
    const float* fc3_b = (const float*)d_in[15];
    float* out = (float*)d_out;              // [0:81920) dcap, [81920:483328) recon

    static float *p_masked = nullptr, *p_r1 = nullptr, *p_r2 = nullptr;
    static float *g_cwT_p = nullptr;
    static bool attrs_set = false;
    if (!p_masked) {
        cudaGetSymbolAddress((void**)&p_masked, g_masked);
        cudaGetSymbolAddress((void**)&p_r1, g_r1);
        cudaGetSymbolAddress((void**)&p_r2, g_r2);
        cudaGetSymbolAddress((void**)&g_cwT_p, g_cwT);
    }
    if (!attrs_set) {
        cudaFuncSetAttribute(prim_mma_kernel, cudaFuncAttributeMaxDynamicSharedMemorySize,
                             PRIM_SMEM);
        cudaFuncSetAttribute(cc_votes_kernel, cudaFuncAttributeMaxDynamicSharedMemorySize,
                             (16384 + 12800) * 4);
        attrs_set = true;
    }

    // weight prep
    prepack_W<<<(25 * 4 * 256 * 64 + 255) / 256, 256>>>(prim_w);
    transpose_oc<<<200, 256>>>(conv_w, g_cwT_p, 256, 200);

    // conv1 + relu (writes bf16 hi/lo, pixel-major)
    conv1_kernel<<<dim3(512, 16), 256>>>(x, conv1_w, conv1_b);

    // primary caps conv via mma.sync + ldmatrix + fused squash
    prim_mma_kernel<<<256, 512, PRIM_SMEM>>>(prim_bias);

    // conv caps votes
    cc_votes_kernel<<<512, 256, (16384 + 12800) * 4>>>();

    // conv caps routing
    cc_routing_kernel<<<2048, 256>>>(conv_bias);

    // digit caps
    digit_kernel<<<512, 256>>>(digit_w, digit_bias, y, out);

    // FC reconstruction chain
    fc_kernel<1><<<dim3(8, 8), 256>>>(p_masked, fc1_w, fc1_b, p_r1, 512, 160, 512);
    fc_kernel<1><<<dim3(16, 8), 256>>>(p_r1, fc2_w, fc2_b, p_r2, 512, 512, 1024);
    fc_kernel<2><<<dim3(13, 8), 256>>>(p_r2, fc3_w, fc3_b, out + 81920, 512, 1024, 784);
}